// round 7
// baseline (speedup 1.0000x reference)
#include <cuda_runtime.h>
#include <cuda_bf16.h>
#include <cstdint>
#include <math.h>

// NOTE: resubmission of the round-5 kernel — the prior bench died to a
// container infra failure ("GB300 container failed twice") before measuring it.

#define B_ 256
#define T_ 512
#define I_ 512
#define H_ 1024
#define G_ 4096   // 4*H

// ==================== device scratch (no allocations allowed) ====================
__device__ float g_pre0[(size_t)256 * B_ * G_];
__device__ float g_pre1[(size_t)256 * B_ * G_];
__device__ __align__(128) __nv_bfloat16 g_x_hi[(size_t)B_ * T_ * I_];
__device__ __align__(128) __nv_bfloat16 g_x_lo[(size_t)B_ * T_ * I_];
__device__ __align__(128) __nv_bfloat16 g_h_hi[2][B_ * H_];
__device__ __align__(128) __nv_bfloat16 g_h_lo[2][B_ * H_];
__device__ __align__(128) __nv_bfloat16 g_Wip_hi[G_ * I_];
__device__ __align__(128) __nv_bfloat16 g_Wip_lo[G_ * I_];
__device__ __align__(128) __nv_bfloat16 g_Whp_hi[G_ * H_];
__device__ __align__(128) __nv_bfloat16 g_Whp_lo[G_ * H_];
__device__ float g_biasp[G_];

// ==================== PTX helpers (plain sm_103 feature set) ====================
__device__ __forceinline__ uint32_t smem_u32(const void* p) {
    uint32_t a;
    asm("{ .reg .u64 t; cvta.to.shared.u64 t, %1; cvt.u32.u64 %0, t; }" : "=r"(a) : "l"(p));
    return a;
}
#define CP16(dst_u32, src_ptr) \
    asm volatile("cp.async.cg.shared.global [%0], [%1], 16;" :: "r"(dst_u32), "l"(src_ptr) : "memory")
#define CP_COMMIT() asm volatile("cp.async.commit_group;" ::: "memory")
#define CP_WAIT2()  asm volatile("cp.async.wait_group 2;" ::: "memory")
#define LDSM4(r0, r1, r2, r3, addr) \
    asm volatile("ldmatrix.sync.aligned.m8n8.x4.shared.b16 {%0,%1,%2,%3}, [%4];" \
        : "=r"(r0), "=r"(r1), "=r"(r2), "=r"(r3) : "r"(addr))
#define MMA_BF16(c, a, b) \
    asm volatile("mma.sync.aligned.m16n8k16.row.col.f32.bf16.bf16.f32 " \
        "{%0,%1,%2,%3}, {%4,%5,%6,%7}, {%8,%9}, {%0,%1,%2,%3};" \
        : "+f"((c)[0]), "+f"((c)[1]), "+f"((c)[2]), "+f"((c)[3]) \
        : "r"((a)[0]), "r"((a)[1]), "r"((a)[2]), "r"((a)[3]), "r"((b)[0]), "r"((b)[1]))

// ==================== smem layout ====================
// stage: A_hi[128][40] A_lo[128][40] B_hi[64][40] B_lo[64][40] (bf16, 40 = 32+8 pad)
#define ASTRIDE_B  80                 // bytes per smem row
#define AH_OFF     0
#define AL_OFF     10240              // 128*80
#define BH_OFF     20480
#define BL_OFF     25600
#define STAGE_B    30720
#define NSTAGE     4
#define SM_PRE     (NSTAGE * STAGE_B)         // 122880: pre tile 128x64 fp32 (32768 B)
#define SM_C       (SM_PRE + 32768)           // 155648: c tile 128x16 fp32 (8192 B)
#define SMEM_BYTES (SM_C + 8192)              // 163840

#define NTHREADS 512

// ==================== stage loader (gmem -> smem via cp.async, 512 threads) ====================
__device__ __forceinline__ void load_stage(uint32_t sb,
                                           const __nv_bfloat16* a_hi, const __nv_bfloat16* a_lo,
                                           const __nv_bfloat16* b_hi, const __nv_bfloat16* b_lo,
                                           int a_stride, int b_stride, int tid) {
    {
        int r = tid >> 2, u = tid & 3;        // 128 rows x 4 units, exactly 512
        uint32_t so = (uint32_t)(r * ASTRIDE_B + u * 16);
        CP16(sb + AH_OFF + so, a_hi + (size_t)r * a_stride + u * 8);
        CP16(sb + AL_OFF + so, a_lo + (size_t)r * a_stride + u * 8);
    }
    if (tid >= 256) {
        int t2 = tid - 256;
        int r = t2 >> 2, u = t2 & 3;          // 64 rows x 4 units
        uint32_t so = (uint32_t)(r * ASTRIDE_B + u * 16);
        CP16(sb + BH_OFF + so, b_hi + (size_t)r * b_stride + u * 8);
        CP16(sb + BL_OFF + so, b_lo + (size_t)r * b_stride + u * 8);
    }
}

// ==================== warp MMA core: one k32 chunk, warp tile 16x32, 3 split terms ====================
__device__ __forceinline__ void compute_chunk(uint32_t sb, int wid, int lane,
                                              float acc[4][4]) {
    const int wm = (wid >> 1) * 16;       // 8 M groups of 16 rows
    const int wn = (wid & 1) * 32;        // 2 N groups of 32 cols
    const uint32_t a_row  = (uint32_t)(lane & 15);
    const uint32_t a_koff = (uint32_t)((lane >> 4) * 16);
    const uint32_t b_row  = (uint32_t)(((lane >> 4) << 3) + (lane & 7));
    const uint32_t b_koff = (uint32_t)(((lane >> 3) & 1) * 16);

#pragma unroll
    for (int ks = 0; ks < 2; ks++) {
        const uint32_t kb = (uint32_t)(ks * 32);
        uint32_t aH[4], aL[4], bH[4][2], bL[4][2];
        {
            uint32_t ad = sb + AH_OFF + (wm + a_row) * ASTRIDE_B + kb + a_koff;
            LDSM4(aH[0], aH[1], aH[2], aH[3], ad);
            LDSM4(aL[0], aL[1], aL[2], aL[3], ad + (AL_OFF - AH_OFF));
        }
#pragma unroll
        for (int p = 0; p < 2; p++) {
            uint32_t bd = sb + BH_OFF + (wn + p * 16 + b_row) * ASTRIDE_B + kb + b_koff;
            LDSM4(bH[2 * p][0], bH[2 * p][1], bH[2 * p + 1][0], bH[2 * p + 1][1], bd);
            LDSM4(bL[2 * p][0], bL[2 * p][1], bL[2 * p + 1][0], bL[2 * p + 1][1],
                  bd + (BL_OFF - BH_OFF));
        }
#pragma unroll
        for (int nt = 0; nt < 4; nt++) {
            MMA_BF16(acc[nt], aH, bH[nt]);
            MMA_BF16(acc[nt], aH, bL[nt]);
            MMA_BF16(acc[nt], aL, bH[nt]);
        }
    }
}

// ==================== init: permute + split weights, bias, h0 ====================
__global__ void permute_init_k(const float* __restrict__ Wi,
                               const float* __restrict__ Wh,
                               const float* __restrict__ bi,
                               const float* __restrict__ bh) {
    int stride = gridDim.x * blockDim.x;
    int tid0 = blockIdx.x * blockDim.x + threadIdx.x;
    for (int idx = tid0; idx < G_ * H_; idx += stride) {
        int jp = idx / H_, i = idx % H_;
        int gate = jp & 3, hh = jp >> 2;
        float w = Wh[(size_t)(gate * H_ + hh) * H_ + i];
        __nv_bfloat16 hi = __float2bfloat16_rn(w);
        g_Whp_hi[idx] = hi;
        g_Whp_lo[idx] = __float2bfloat16_rn(w - __bfloat162float(hi));
    }
    for (int idx = tid0; idx < G_ * I_; idx += stride) {
        int jp = idx / I_, i = idx % I_;
        int gate = jp & 3, hh = jp >> 2;
        float w = Wi[(size_t)(gate * H_ + hh) * I_ + i];
        __nv_bfloat16 hi = __float2bfloat16_rn(w);
        g_Wip_hi[idx] = hi;
        g_Wip_lo[idx] = __float2bfloat16_rn(w - __bfloat162float(hi));
    }
    for (int idx = tid0; idx < G_; idx += stride) {
        int gate = idx & 3, hh = idx >> 2;
        int j = gate * H_ + hh;
        g_biasp[idx] = bi[j] + bh[j];
    }
    for (int idx = tid0; idx < B_ * H_; idx += stride) {
        g_h_hi[0][idx] = __float2bfloat16_rn(0.0f);
        g_h_lo[0][idx] = __float2bfloat16_rn(0.0f);
    }
}

// ==================== split x into bf16 hi/lo ====================
__global__ void split_x_k(const float* __restrict__ x) {
    size_t n4 = (size_t)B_ * T_ * I_ / 4;
    size_t stride = (size_t)gridDim.x * blockDim.x;
    for (size_t i = blockIdx.x * blockDim.x + threadIdx.x; i < n4; i += stride) {
        float4 v = ((const float4*)x)[i];
        __nv_bfloat16 h0 = __float2bfloat16_rn(v.x);
        __nv_bfloat16 h1 = __float2bfloat16_rn(v.y);
        __nv_bfloat16 h2 = __float2bfloat16_rn(v.z);
        __nv_bfloat16 h3 = __float2bfloat16_rn(v.w);
        __nv_bfloat162* dhi = (__nv_bfloat162*)(g_x_hi + i * 4);
        __nv_bfloat162* dlo = (__nv_bfloat162*)(g_x_lo + i * 4);
        dhi[0] = __nv_bfloat162(h0, h1);
        dhi[1] = __nv_bfloat162(h2, h3);
        dlo[0] = __nv_bfloat162(__float2bfloat16_rn(v.x - __bfloat162float(h0)),
                                __float2bfloat16_rn(v.y - __bfloat162float(h1)));
        dlo[1] = __nv_bfloat162(__float2bfloat16_rn(v.z - __bfloat162float(h2)),
                                __float2bfloat16_rn(v.w - __bfloat162float(h3)));
    }
}

// ==================== pregemm: pre[t][b][j'] = x . WipT + bias (HMMA, split) ====================
__global__ void __launch_bounds__(NTHREADS, 1) pregemm_k() {
    extern __shared__ char smem[];
    const uint32_t sm0 = smem_u32(smem);
    const int tid = threadIdx.x;
    const int wid = tid >> 5, lane = tid & 31;
    const int mb = blockIdx.x * 128;
    const int cb = blockIdx.y * 64;

    const __nv_bfloat16* a_hi = g_x_hi + (size_t)mb * I_;
    const __nv_bfloat16* a_lo = g_x_lo + (size_t)mb * I_;
    const __nv_bfloat16* b_hi = g_Wip_hi + (size_t)cb * I_;
    const __nv_bfloat16* b_lo = g_Wip_lo + (size_t)cb * I_;

    float acc[4][4] = {};

#pragma unroll
    for (int s = 0; s < 3; s++) {
        load_stage(sm0 + s * STAGE_B, a_hi + s * 32, a_lo + s * 32,
                   b_hi + s * 32, b_lo + s * 32, I_, I_, tid);
        CP_COMMIT();
    }
#pragma unroll 1
    for (int ch = 0; ch < 16; ch++) {
        CP_WAIT2();
        __syncthreads();
        if (ch + 3 < 16) {
            load_stage(sm0 + ((ch + 3) & 3) * STAGE_B,
                       a_hi + (ch + 3) * 32, a_lo + (ch + 3) * 32,
                       b_hi + (ch + 3) * 32, b_lo + (ch + 3) * 32, I_, I_, tid);
        }
        CP_COMMIT();
        compute_chunk(sm0 + (ch & 3) * STAGE_B, wid, lane, acc);
    }

    // epilogue: + bias, scatter to pre[t][b][j']
    const int wm = (wid >> 1) * 16;
    const int wn = (wid & 1) * 32;
    const int qr = lane >> 2, qc = 2 * (lane & 3);
#pragma unroll
    for (int half = 0; half < 2; half++) {
        int r = wm + qr + half * 8;
        int m = mb + r;
        int b = m >> 9, tt = m & 511;
        float* preh = (tt < 256 ? g_pre0 : g_pre1);
        float* dst = preh + (size_t)(tt & 255) * B_ * G_ + (size_t)b * G_ + cb;
#pragma unroll
        for (int nt = 0; nt < 4; nt++) {
            int col = wn + nt * 8 + qc;
            dst[col]     = acc[nt][half * 2 + 0] + g_biasp[cb + col];
            dst[col + 1] = acc[nt][half * 2 + 1] + g_biasp[cb + col + 1];
        }
    }
}

// ==================== one LSTM step (HMMA, deep pipeline, fused epilogue) ====================
__device__ __forceinline__ float sigm(float v) { return 1.0f / (1.0f + expf(-v)); }

__global__ void __launch_bounds__(NTHREADS, 1) step_k(float* __restrict__ c, int t) {
    extern __shared__ char smem[];
    const uint32_t sm0 = smem_u32(smem);
    const int tid = threadIdx.x;
    const int wid = tid >> 5, lane = tid & 31;
    const int rb = blockIdx.x * 128;
    const int cb = blockIdx.y * 64;
    const int hb = cb >> 2;

    const __nv_bfloat16* a_hi = g_h_hi[t & 1] + (size_t)rb * H_;
    const __nv_bfloat16* a_lo = g_h_lo[t & 1] + (size_t)rb * H_;
    const __nv_bfloat16* b_hi = g_Whp_hi + (size_t)cb * H_;
    const __nv_bfloat16* b_lo = g_Whp_lo + (size_t)cb * H_;
    __nv_bfloat16* __restrict__ hout_hi = g_h_hi[(t & 1) ^ 1];
    __nv_bfloat16* __restrict__ hout_lo = g_h_lo[(t & 1) ^ 1];

    const float* preh = (t < 256 ? g_pre0 : g_pre1);
    const float* prebase = preh + (size_t)(t & 255) * B_ * G_;

    float acc[4][4] = {};

    // ---- prologue: stage 0 group also prefetches pre + c tiles into smem ----
    load_stage(sm0, a_hi, a_lo, b_hi, b_lo, H_, H_, tid);
    {
        // pre tile: 128 rows x 64 fp32 (16 x 16B units per row) = 2048 units
#pragma unroll
        for (int i = 0; i < 4; i++) {
            int u = tid + i * NTHREADS;
            int r = u >> 4, q = u & 15;
            CP16(sm0 + SM_PRE + (uint32_t)u * 16,
                 prebase + (size_t)(rb + r) * G_ + cb + q * 4);
        }
        // c tile: 128 rows x 16 fp32 (4 x 16B units per row) = 512 units
        {
            int r = tid >> 2, q = tid & 3;
            CP16(sm0 + SM_C + (uint32_t)tid * 16,
                 c + (size_t)(rb + r) * H_ + hb + q * 4);
        }
    }
    CP_COMMIT();
#pragma unroll
    for (int s = 1; s < 3; s++) {
        load_stage(sm0 + s * STAGE_B, a_hi + s * 32, a_lo + s * 32,
                   b_hi + s * 32, b_lo + s * 32, H_, H_, tid);
        CP_COMMIT();
    }

    // ---- mainloop: one barrier per chunk, loads 3 chunks ahead ----
#pragma unroll 1
    for (int ch = 0; ch < 32; ch++) {
        CP_WAIT2();
        __syncthreads();
        if (ch + 3 < 32) {
            load_stage(sm0 + ((ch + 3) & 3) * STAGE_B,
                       a_hi + (ch + 3) * 32, a_lo + (ch + 3) * 32,
                       b_hi + (ch + 3) * 32, b_lo + (ch + 3) * 32, H_, H_, tid);
        }
        CP_COMMIT();
        compute_chunk(sm0 + (ch & 3) * STAGE_B, wid, lane, acc);
    }

    // ---- park gates in smem (reuses stages 0/1, free by now) ----
    float* Gs = (float*)smem;
    const int wm = (wid >> 1) * 16;
    const int wn = (wid & 1) * 32;
    const int qr = lane >> 2, qc = 2 * (lane & 3);
    __syncthreads();
#pragma unroll
    for (int nt = 0; nt < 4; nt++) {
        int r0 = wm + qr;
        int cc = wn + nt * 8 + qc;
        Gs[r0 * 68 + cc]           = acc[nt][0];
        Gs[r0 * 68 + cc + 1]       = acc[nt][1];
        Gs[(r0 + 8) * 68 + cc]     = acc[nt][2];
        Gs[(r0 + 8) * 68 + cc + 1] = acc[nt][3];
    }
    __syncthreads();

    // ---- activations + state update, all operands in smem ----
    const float4* PreS = (const float4*)(smem + SM_PRE);   // [128][16] float4
    const float*  CS   = (const float*)(smem + SM_C);      // [128][16]
#pragma unroll
    for (int it = tid; it < 128 * 16; it += NTHREADS) {
        int r = it >> 4, hh = it & 15;
        float4 g = *(const float4*)&Gs[r * 68 + hh * 4];
        float4 p = PreS[r * 16 + hh];
        float iv = sigm(g.x + p.x);
        float fv = sigm(g.y + p.y);
        float gv = tanhf(g.z + p.z);
        float ov = sigm(g.w + p.w);
        size_t idx = (size_t)(rb + r) * H_ + hb + hh;
        float cn = fv * CS[r * 16 + hh] + iv * gv;
        c[idx] = cn;
        float hn = ov * tanhf(cn);
        __nv_bfloat16 hi = __float2bfloat16_rn(hn);
        hout_hi[idx] = hi;
        hout_lo[idx] = __float2bfloat16_rn(hn - __bfloat162float(hi));
    }
}

// ==================== launch ====================
extern "C" void kernel_launch(void* const* d_in, const int* in_sizes, int n_in,
                              void* d_out, int out_size) {
    const float* x  = (const float*)d_in[0];
    const float* Wi = (const float*)d_in[1];
    const float* Wh = (const float*)d_in[2];
    const float* bi = (const float*)d_in[3];
    const float* bh = (const float*)d_in[4];
    const float* c0 = (const float*)d_in[5];
    float* c = (float*)d_out;

    static bool attr_set = false;
    if (!attr_set) {
        cudaFuncSetAttribute(pregemm_k, cudaFuncAttributeMaxDynamicSharedMemorySize, SMEM_BYTES);
        cudaFuncSetAttribute(step_k,    cudaFuncAttributeMaxDynamicSharedMemorySize, SMEM_BYTES);
        attr_set = true;
    }

    cudaMemcpyAsync(c, c0, sizeof(float) * B_ * H_, cudaMemcpyDeviceToDevice);

    split_x_k<<<4096, 256>>>(x);
    permute_init_k<<<512, 256>>>(Wi, Wh, bi, bh);

    pregemm_k<<<dim3((B_ * T_) / 128, G_ / 64), NTHREADS, SMEM_BYTES>>>();

    for (int t = 0; t < T_; t++) {
        step_k<<<dim3(B_ / 128, G_ / 64), NTHREADS, SMEM_BYTES>>>(c, t);
    }
}

// round 9
// speedup vs baseline: 1.1615x; 1.1615x over previous
#include <cuda_runtime.h>
#include <cuda_bf16.h>
#include <cstdint>
#include <math.h>

#define B_ 256
#define T_ 512
#define I_ 512
#define H_ 1024
#define G_ 4096   // 4*H

// ==================== device scratch (no allocations allowed) ====================
__device__ float g_pre0[(size_t)256 * B_ * G_];
__device__ float g_pre1[(size_t)256 * B_ * G_];
__device__ __align__(128) __nv_bfloat16 g_x_hi[(size_t)B_ * T_ * I_];
__device__ __align__(128) __nv_bfloat16 g_x_lo[(size_t)B_ * T_ * I_];
__device__ __align__(128) __nv_bfloat16 g_h_hi[2][B_ * H_];
__device__ __align__(128) __nv_bfloat16 g_h_lo[2][B_ * H_];
__device__ __align__(128) __nv_bfloat16 g_Wip_hi[G_ * I_];
__device__ __align__(128) __nv_bfloat16 g_Wip_lo[G_ * I_];
__device__ __align__(128) __nv_bfloat16 g_Whp_hi[G_ * H_];
__device__ __align__(128) __nv_bfloat16 g_Whp_lo[G_ * H_];
__device__ float g_biasp[G_];

// ==================== PTX helpers (plain sm_103 feature set) ====================
__device__ __forceinline__ uint32_t smem_u32(const void* p) {
    uint32_t a;
    asm("{ .reg .u64 t; cvta.to.shared.u64 t, %1; cvt.u32.u64 %0, t; }" : "=r"(a) : "l"(p));
    return a;
}
#define CP16(dst_u32, src_ptr) \
    asm volatile("cp.async.cg.shared.global [%0], [%1], 16;" :: "r"(dst_u32), "l"(src_ptr) : "memory")
#define CP_COMMIT() asm volatile("cp.async.commit_group;" ::: "memory")
#define CP_WAIT2()  asm volatile("cp.async.wait_group 2;" ::: "memory")
#define CP_WAIT_ALL() asm volatile("cp.async.wait_all;" ::: "memory")
#define CP_MBAR_ARRIVE_NOINC(addr) \
    asm volatile("cp.async.mbarrier.arrive.noinc.shared.b64 [%0];" :: "r"((uint32_t)(addr)) : "memory")
#define MBARRIER_INIT(addr, cnt) \
    asm volatile("mbarrier.init.shared.b64 [%0], %1;" :: "r"((uint32_t)(addr)), "r"((uint32_t)(cnt)) : "memory")
#define MBARRIER_ARRIVE(addr) \
    asm volatile("mbarrier.arrive.shared.b64 _, [%0];" :: "r"((uint32_t)(addr)) : "memory")
#define MBARRIER_WAIT_PARITY(addr, par) do { \
    uint32_t _m = (uint32_t)(addr); uint32_t _p = (uint32_t)(par); uint32_t _d; \
    asm volatile("{\n\t.reg .pred p;\n\tmbarrier.try_wait.parity.acquire.cta.shared::cta.b64 p, [%1], %2;\n\tselp.b32 %0, 1, 0, p;\n\t}" \
        : "=r"(_d) : "r"(_m), "r"(_p) : "memory"); \
    if (!_d) { \
        asm volatile("{\n\t.reg .pred P1;\n\tWL_%=:\n\tmbarrier.try_wait.parity.acquire.cta.shared::cta.b64 P1, [%0], %1, 0x989680;\n\t@P1 bra.uni WD_%=;\n\tbra.uni WL_%=;\n\tWD_%=:\n\t}" \
            :: "r"(_m), "r"(_p) : "memory"); \
    } } while (0)
#define LDSM4(r0, r1, r2, r3, addr) \
    asm volatile("ldmatrix.sync.aligned.m8n8.x4.shared.b16 {%0,%1,%2,%3}, [%4];" \
        : "=r"(r0), "=r"(r1), "=r"(r2), "=r"(r3) : "r"(addr))
#define MMA_BF16(c, a, b) \
    asm volatile("mma.sync.aligned.m16n8k16.row.col.f32.bf16.bf16.f32 " \
        "{%0,%1,%2,%3}, {%4,%5,%6,%7}, {%8,%9}, {%0,%1,%2,%3};" \
        : "+f"((c)[0]), "+f"((c)[1]), "+f"((c)[2]), "+f"((c)[3]) \
        : "r"((a)[0]), "r"((a)[1]), "r"((a)[2]), "r"((a)[3]), "r"((b)[0]), "r"((b)[1]))

// ==================== smem layout ====================
// stage: A_hi[128][40] A_lo[128][40] B_hi[64][40] B_lo[64][40] (bf16, 40 = 32+8 pad)
#define ASTRIDE_B  80                 // bytes per smem row
#define AH_OFF     0
#define AL_OFF     10240              // 128*80
#define BH_OFF     20480
#define BL_OFF     25600
#define STAGE_B    30720
#define NSTAGE     4
#define SM_PRE     (NSTAGE * STAGE_B)         // 122880: pre tile 128x64 fp32 (32768 B)
#define SM_C       (SM_PRE + 32768)           // 155648: c tile 128x16 fp32 (8192 B)
#define SM_MBAR    (SM_C + 8192)              // 163840: full[4] then consumed[4]
#define SMEM_BYTES (SM_MBAR + 64)             // 163904

#define NCONS      512                // 16 consumer warps
#define NPROD      128                // 4 producer warps
#define NTOT       (NCONS + NPROD)    // 640

// ==================== warp MMA core: one k32 chunk, warp tile 16x32, 3 split terms ====================
__device__ __forceinline__ void compute_chunk(uint32_t sb, int wid, int lane,
                                              float acc[4][4]) {
    const int wm = (wid >> 1) * 16;       // 8 M groups of 16 rows
    const int wn = (wid & 1) * 32;        // 2 N groups of 32 cols
    const uint32_t a_row  = (uint32_t)(lane & 15);
    const uint32_t a_koff = (uint32_t)((lane >> 4) * 16);
    const uint32_t b_row  = (uint32_t)(((lane >> 4) << 3) + (lane & 7));
    const uint32_t b_koff = (uint32_t)(((lane >> 3) & 1) * 16);

#pragma unroll
    for (int ks = 0; ks < 2; ks++) {
        const uint32_t kb = (uint32_t)(ks * 32);
        uint32_t aH[4], aL[4], bH[4][2], bL[4][2];
        {
            uint32_t ad = sb + AH_OFF + (wm + a_row) * ASTRIDE_B + kb + a_koff;
            LDSM4(aH[0], aH[1], aH[2], aH[3], ad);
            LDSM4(aL[0], aL[1], aL[2], aL[3], ad + (AL_OFF - AH_OFF));
        }
#pragma unroll
        for (int p = 0; p < 2; p++) {
            uint32_t bd = sb + BH_OFF + (wn + p * 16 + b_row) * ASTRIDE_B + kb + b_koff;
            LDSM4(bH[2 * p][0], bH[2 * p][1], bH[2 * p + 1][0], bH[2 * p + 1][1], bd);
            LDSM4(bL[2 * p][0], bL[2 * p][1], bL[2 * p + 1][0], bL[2 * p + 1][1],
                  bd + (BL_OFF - BH_OFF));
        }
#pragma unroll
        for (int nt = 0; nt < 4; nt++) {
            MMA_BF16(acc[nt], aH, bH[nt]);
            MMA_BF16(acc[nt], aH, bL[nt]);
            MMA_BF16(acc[nt], aL, bH[nt]);
        }
    }
}

// ==================== init: permute + split weights, bias, h0 ====================
__global__ void permute_init_k(const float* __restrict__ Wi,
                               const float* __restrict__ Wh,
                               const float* __restrict__ bi,
                               const float* __restrict__ bh) {
    int stride = gridDim.x * blockDim.x;
    int tid0 = blockIdx.x * blockDim.x + threadIdx.x;
    for (int idx = tid0; idx < G_ * H_; idx += stride) {
        int jp = idx / H_, i = idx % H_;
        int gate = jp & 3, hh = jp >> 2;
        float w = Wh[(size_t)(gate * H_ + hh) * H_ + i];
        __nv_bfloat16 hi = __float2bfloat16_rn(w);
        g_Whp_hi[idx] = hi;
        g_Whp_lo[idx] = __float2bfloat16_rn(w - __bfloat162float(hi));
    }
    for (int idx = tid0; idx < G_ * I_; idx += stride) {
        int jp = idx / I_, i = idx % I_;
        int gate = jp & 3, hh = jp >> 2;
        float w = Wi[(size_t)(gate * H_ + hh) * I_ + i];
        __nv_bfloat16 hi = __float2bfloat16_rn(w);
        g_Wip_hi[idx] = hi;
        g_Wip_lo[idx] = __float2bfloat16_rn(w - __bfloat162float(hi));
    }
    for (int idx = tid0; idx < G_; idx += stride) {
        int gate = idx & 3, hh = idx >> 2;
        int j = gate * H_ + hh;
        g_biasp[idx] = bi[j] + bh[j];
    }
    for (int idx = tid0; idx < B_ * H_; idx += stride) {
        g_h_hi[0][idx] = __float2bfloat16_rn(0.0f);
        g_h_lo[0][idx] = __float2bfloat16_rn(0.0f);
    }
}

// ==================== split x into bf16 hi/lo ====================
__global__ void split_x_k(const float* __restrict__ x) {
    size_t n4 = (size_t)B_ * T_ * I_ / 4;
    size_t stride = (size_t)gridDim.x * blockDim.x;
    for (size_t i = blockIdx.x * blockDim.x + threadIdx.x; i < n4; i += stride) {
        float4 v = ((const float4*)x)[i];
        __nv_bfloat16 h0 = __float2bfloat16_rn(v.x);
        __nv_bfloat16 h1 = __float2bfloat16_rn(v.y);
        __nv_bfloat16 h2 = __float2bfloat16_rn(v.z);
        __nv_bfloat16 h3 = __float2bfloat16_rn(v.w);
        __nv_bfloat162* dhi = (__nv_bfloat162*)(g_x_hi + i * 4);
        __nv_bfloat162* dlo = (__nv_bfloat162*)(g_x_lo + i * 4);
        dhi[0] = __nv_bfloat162(h0, h1);
        dhi[1] = __nv_bfloat162(h2, h3);
        dlo[0] = __nv_bfloat162(__float2bfloat16_rn(v.x - __bfloat162float(h0)),
                                __float2bfloat16_rn(v.y - __bfloat162float(h1)));
        dlo[1] = __nv_bfloat162(__float2bfloat16_rn(v.z - __bfloat162float(h2)),
                                __float2bfloat16_rn(v.w - __bfloat162float(h3)));
    }
}

// ==================== pregemm (round-7 structure, 512 threads) ====================
__device__ __forceinline__ void load_stage512(uint32_t sb,
                                              const __nv_bfloat16* a_hi, const __nv_bfloat16* a_lo,
                                              const __nv_bfloat16* b_hi, const __nv_bfloat16* b_lo,
                                              int a_stride, int b_stride, int tid) {
    {
        int r = tid >> 2, u = tid & 3;
        uint32_t so = (uint32_t)(r * ASTRIDE_B + u * 16);
        CP16(sb + AH_OFF + so, a_hi + (size_t)r * a_stride + u * 8);
        CP16(sb + AL_OFF + so, a_lo + (size_t)r * a_stride + u * 8);
    }
    if (tid >= 256) {
        int t2 = tid - 256;
        int r = t2 >> 2, u = t2 & 3;
        uint32_t so = (uint32_t)(r * ASTRIDE_B + u * 16);
        CP16(sb + BH_OFF + so, b_hi + (size_t)r * b_stride + u * 8);
        CP16(sb + BL_OFF + so, b_lo + (size_t)r * b_stride + u * 8);
    }
}

__global__ void __launch_bounds__(512, 1) pregemm_k() {
    extern __shared__ char smem[];
    const uint32_t sm0 = smem_u32(smem);
    const int tid = threadIdx.x;
    const int wid = tid >> 5, lane = tid & 31;
    const int mb = blockIdx.x * 128;
    const int cb = blockIdx.y * 64;

    const __nv_bfloat16* a_hi = g_x_hi + (size_t)mb * I_;
    const __nv_bfloat16* a_lo = g_x_lo + (size_t)mb * I_;
    const __nv_bfloat16* b_hi = g_Wip_hi + (size_t)cb * I_;
    const __nv_bfloat16* b_lo = g_Wip_lo + (size_t)cb * I_;

    float acc[4][4] = {};

#pragma unroll
    for (int s = 0; s < 3; s++) {
        load_stage512(sm0 + s * STAGE_B, a_hi + s * 32, a_lo + s * 32,
                      b_hi + s * 32, b_lo + s * 32, I_, I_, tid);
        CP_COMMIT();
    }
#pragma unroll 1
    for (int ch = 0; ch < 16; ch++) {
        CP_WAIT2();
        __syncthreads();
        if (ch + 3 < 16) {
            load_stage512(sm0 + ((ch + 3) & 3) * STAGE_B,
                          a_hi + (ch + 3) * 32, a_lo + (ch + 3) * 32,
                          b_hi + (ch + 3) * 32, b_lo + (ch + 3) * 32, I_, I_, tid);
        }
        CP_COMMIT();
        compute_chunk(sm0 + (ch & 3) * STAGE_B, wid, lane, acc);
    }

    const int wm = (wid >> 1) * 16;
    const int wn = (wid & 1) * 32;
    const int qr = lane >> 2, qc = 2 * (lane & 3);
#pragma unroll
    for (int half = 0; half < 2; half++) {
        int r = wm + qr + half * 8;
        int m = mb + r;
        int b = m >> 9, tt = m & 511;
        float* preh = (tt < 256 ? g_pre0 : g_pre1);
        float* dst = preh + (size_t)(tt & 255) * B_ * G_ + (size_t)b * G_ + cb;
#pragma unroll
        for (int nt = 0; nt < 4; nt++) {
            int col = wn + nt * 8 + qc;
            dst[col]     = acc[nt][half * 2 + 0] + g_biasp[cb + col];
            dst[col + 1] = acc[nt][half * 2 + 1] + g_biasp[cb + col + 1];
        }
    }
}

// ==================== LSTM step: warp-specialized producer/consumer ====================
__device__ __forceinline__ float sigm(float v) { return 1.0f / (1.0f + expf(-v)); }

__global__ void __launch_bounds__(NTOT, 1) step_k(float* __restrict__ c, int t) {
    extern __shared__ char smem[];
    const uint32_t sm0 = smem_u32(smem);
    const int tid = threadIdx.x;
    const int wid = tid >> 5, lane = tid & 31;
    const int rb = blockIdx.x * 128;
    const int cb = blockIdx.y * 64;
    const int hb = cb >> 2;

    const __nv_bfloat16* a_hi = g_h_hi[t & 1] + (size_t)rb * H_;
    const __nv_bfloat16* a_lo = g_h_lo[t & 1] + (size_t)rb * H_;
    const __nv_bfloat16* b_hi = g_Whp_hi + (size_t)cb * H_;
    const __nv_bfloat16* b_lo = g_Whp_lo + (size_t)cb * H_;
    __nv_bfloat16* __restrict__ hout_hi = g_h_hi[(t & 1) ^ 1];
    __nv_bfloat16* __restrict__ hout_lo = g_h_lo[(t & 1) ^ 1];

    const float* preh = (t < 256 ? g_pre0 : g_pre1);
    const float* prebase = preh + (size_t)(t & 255) * B_ * G_;

    const uint32_t mb_full = sm0 + SM_MBAR;          // full[s] at +s*8
    const uint32_t mb_cons = sm0 + SM_MBAR + 32;     // consumed[s] at +s*8

    if (tid == 0) {
#pragma unroll
        for (int s = 0; s < NSTAGE; s++) {
            MBARRIER_INIT(mb_full + s * 8, NPROD);   // 128 async arrivals (noinc)
            MBARRIER_INIT(mb_cons + s * 8, 16);      // 16 consumer-warp arrivals
        }
    }
    __syncthreads();

    float acc[4][4] = {};

    if (wid >= 16) {
        // ======== PRODUCER warps (4 warps, 128 threads) ========
        const int ptid = tid - NCONS;   // 0..127

        // prologue: epilogue operands via cp.async (complete by wait_all below)
#pragma unroll
        for (int j = 0; j < 16; j++) {           // pre tile: 2048 x 16B units
            int u = ptid + j * NPROD;
            int r = u >> 4, q = u & 15;
            CP16(sm0 + SM_PRE + (uint32_t)u * 16,
                 prebase + (size_t)(rb + r) * G_ + cb + q * 4);
        }
#pragma unroll
        for (int j = 0; j < 4; j++) {            // c tile: 512 x 16B units
            int u = ptid + j * NPROD;
            int r = u >> 2, q = u & 3;
            CP16(sm0 + SM_C + (uint32_t)u * 16,
                 c + (size_t)(rb + r) * H_ + hb + q * 4);
        }

#pragma unroll 1
        for (int ch = 0; ch < 32; ch++) {
            const int s = ch & 3;
            const int round = ch >> 2;
            if (round >= 1) {
                MBARRIER_WAIT_PARITY(mb_cons + s * 8, (round - 1) & 1);
            }
            const uint32_t sb = sm0 + s * STAGE_B;
            const int k0 = ch * 32;
            // A hi/lo: 512 units each (128 rows x 4)
#pragma unroll
            for (int j = 0; j < 4; j++) {
                int u = ptid + j * NPROD;
                int r = u >> 2, c16 = u & 3;
                uint32_t so = (uint32_t)(r * ASTRIDE_B + c16 * 16);
                CP16(sb + AH_OFF + so, a_hi + (size_t)r * H_ + k0 + c16 * 8);
                CP16(sb + AL_OFF + so, a_lo + (size_t)r * H_ + k0 + c16 * 8);
            }
            // B hi/lo: 256 units each (64 rows x 4)
#pragma unroll
            for (int j = 0; j < 2; j++) {
                int u = ptid + j * NPROD;
                int r = u >> 2, c16 = u & 3;
                uint32_t so = (uint32_t)(r * ASTRIDE_B + c16 * 16);
                CP16(sb + BH_OFF + so, b_hi + (size_t)r * H_ + k0 + c16 * 8);
                CP16(sb + BL_OFF + so, b_lo + (size_t)r * H_ + k0 + c16 * 8);
            }
            CP_MBAR_ARRIVE_NOINC(mb_full + s * 8);
        }
        CP_WAIT_ALL();
    } else {
        // ======== CONSUMER warps (16 warps): free-running, no CTA barrier ========
#pragma unroll 1
        for (int ch = 0; ch < 32; ch++) {
            const int s = ch & 3;
            const int round = ch >> 2;
            MBARRIER_WAIT_PARITY(mb_full + s * 8, round & 1);
            compute_chunk(sm0 + s * STAGE_B, wid, lane, acc);
            __syncwarp();
            if (lane == 0) MBARRIER_ARRIVE(mb_cons + s * 8);
        }
    }

    // ---- uniform convergence: ALL 640 threads hit the same barriers ----
    __syncthreads();   // stages dead; producers' epilogue cp.asyncs complete

    if (wid < 16) {
        float* Gs = (float*)smem;  // overlays stages 0/1 (dead)
        const int wm = (wid >> 1) * 16;
        const int wn = (wid & 1) * 32;
        const int qr = lane >> 2, qc = 2 * (lane & 3);
#pragma unroll
        for (int nt = 0; nt < 4; nt++) {
            int r0 = wm + qr;
            int cc = wn + nt * 8 + qc;
            Gs[r0 * 68 + cc]           = acc[nt][0];
            Gs[r0 * 68 + cc + 1]       = acc[nt][1];
            Gs[(r0 + 8) * 68 + cc]     = acc[nt][2];
            Gs[(r0 + 8) * 68 + cc + 1] = acc[nt][3];
        }
    }
    __syncthreads();

    // ---- activations + state update, all operands in smem (all 640 threads) ----
    {
        const float* Gs = (const float*)smem;
        const float4* PreS = (const float4*)(smem + SM_PRE);   // [128][16] float4
        const float*  CS   = (const float*)(smem + SM_C);      // [128][16]
        for (int it = tid; it < 128 * 16; it += NTOT) {
            int r = it >> 4, hh = it & 15;
            float4 g = *(const float4*)&Gs[r * 68 + hh * 4];
            float4 p = PreS[r * 16 + hh];
            float iv = sigm(g.x + p.x);
            float fv = sigm(g.y + p.y);
            float gv = tanhf(g.z + p.z);
            float ov = sigm(g.w + p.w);
            size_t idx = (size_t)(rb + r) * H_ + hb + hh;
            float cn = fv * CS[r * 16 + hh] + iv * gv;
            c[idx] = cn;
            float hn = ov * tanhf(cn);
            __nv_bfloat16 hi = __float2bfloat16_rn(hn);
            hout_hi[idx] = hi;
            hout_lo[idx] = __float2bfloat16_rn(hn - __bfloat162float(hi));
        }
    }
}

// ==================== launch ====================
extern "C" void kernel_launch(void* const* d_in, const int* in_sizes, int n_in,
                              void* d_out, int out_size) {
    const float* x  = (const float*)d_in[0];
    const float* Wi = (const float*)d_in[1];
    const float* Wh = (const float*)d_in[2];
    const float* bi = (const float*)d_in[3];
    const float* bh = (const float*)d_in[4];
    const float* c0 = (const float*)d_in[5];
    float* c = (float*)d_out;

    static bool attr_set = false;
    if (!attr_set) {
        cudaFuncSetAttribute(pregemm_k, cudaFuncAttributeMaxDynamicSharedMemorySize, SMEM_BYTES);
        cudaFuncSetAttribute(step_k,    cudaFuncAttributeMaxDynamicSharedMemorySize, SMEM_BYTES);
        attr_set = true;
    }

    cudaMemcpyAsync(c, c0, sizeof(float) * B_ * H_, cudaMemcpyDeviceToDevice);

    split_x_k<<<4096, 256>>>(x);
    permute_init_k<<<512, 256>>>(Wi, Wh, bi, bh);

    pregemm_k<<<dim3((B_ * T_) / 128, G_ / 64), 512, SMEM_BYTES>>>();

    for (int t = 0; t < T_; t++) {
        step_k<<<dim3(B_ / 128, G_ / 64), NTOT, SMEM_BYTES>>>(c, t);
    }
}

// round 11
// speedup vs baseline: 1.1852x; 1.0204x over previous
#include <cuda_runtime.h>
#include <cuda_bf16.h>
#include <cstdint>
#include <math.h>

// NOTE: resubmission of the round-10 kernel. That bench died to
// "GB300 container failed twice" with no compile/runtime diagnostic; audit
// found no barrier-divergence or deadlock path (protocol identical to the
// passing round-9 kernel, scaled M=128->64). Precedent: round 5 flaked the
// same way and the identical kernel passed in round 7.

#define B_ 256
#define T_ 512
#define I_ 512
#define H_ 1024
#define G_ 4096   // 4*H

// ==================== device scratch (no allocations allowed) ====================
__device__ float g_pre0[(size_t)256 * B_ * G_];
__device__ float g_pre1[(size_t)256 * B_ * G_];
__device__ __align__(128) __nv_bfloat16 g_x_hi[(size_t)B_ * T_ * I_];
__device__ __align__(128) __nv_bfloat16 g_x_lo[(size_t)B_ * T_ * I_];
__device__ __align__(128) __nv_bfloat16 g_h_hi[2][B_ * H_];
__device__ __align__(128) __nv_bfloat16 g_h_lo[2][B_ * H_];
__device__ __align__(128) __nv_bfloat16 g_Wip_hi[G_ * I_];
__device__ __align__(128) __nv_bfloat16 g_Wip_lo[G_ * I_];
__device__ __align__(128) __nv_bfloat16 g_Whp_hi[G_ * H_];
__device__ __align__(128) __nv_bfloat16 g_Whp_lo[G_ * H_];
__device__ float g_biasp[G_];

// ==================== PTX helpers (plain sm_103 feature set) ====================
__device__ __forceinline__ uint32_t smem_u32(const void* p) {
    uint32_t a;
    asm("{ .reg .u64 t; cvta.to.shared.u64 t, %1; cvt.u32.u64 %0, t; }" : "=r"(a) : "l"(p));
    return a;
}
#define CP16(dst_u32, src_ptr) \
    asm volatile("cp.async.cg.shared.global [%0], [%1], 16;" :: "r"(dst_u32), "l"(src_ptr) : "memory")
#define CP_COMMIT() asm volatile("cp.async.commit_group;" ::: "memory")
#define CP_WAIT1()  asm volatile("cp.async.wait_group 1;" ::: "memory")
#define CP_WAIT_ALL() asm volatile("cp.async.wait_all;" ::: "memory")
#define CP_MBAR_ARRIVE_NOINC(addr) \
    asm volatile("cp.async.mbarrier.arrive.noinc.shared.b64 [%0];" :: "r"((uint32_t)(addr)) : "memory")
#define MBARRIER_INIT(addr, cnt) \
    asm volatile("mbarrier.init.shared.b64 [%0], %1;" :: "r"((uint32_t)(addr)), "r"((uint32_t)(cnt)) : "memory")
#define MBARRIER_ARRIVE(addr) \
    asm volatile("mbarrier.arrive.shared.b64 _, [%0];" :: "r"((uint32_t)(addr)) : "memory")
#define MBARRIER_WAIT_PARITY(addr, par) do { \
    uint32_t _m = (uint32_t)(addr); uint32_t _p = (uint32_t)(par); uint32_t _d; \
    asm volatile("{\n\t.reg .pred p;\n\tmbarrier.try_wait.parity.acquire.cta.shared::cta.b64 p, [%1], %2;\n\tselp.b32 %0, 1, 0, p;\n\t}" \
        : "=r"(_d) : "r"(_m), "r"(_p) : "memory"); \
    if (!_d) { \
        asm volatile("{\n\t.reg .pred P1;\n\tWL_%=:\n\tmbarrier.try_wait.parity.acquire.cta.shared::cta.b64 P1, [%0], %1, 0x989680;\n\t@P1 bra.uni WD_%=;\n\tbra.uni WL_%=;\n\tWD_%=:\n\t}" \
            :: "r"(_m), "r"(_p) : "memory"); \
    } } while (0)
#define LDSM4(r0, r1, r2, r3, addr) \
    asm volatile("ldmatrix.sync.aligned.m8n8.x4.shared.b16 {%0,%1,%2,%3}, [%4];" \
        : "=r"(r0), "=r"(r1), "=r"(r2), "=r"(r3) : "r"(addr))
#define MMA_BF16(c, a, b) \
    asm volatile("mma.sync.aligned.m16n8k16.row.col.f32.bf16.bf16.f32 " \
        "{%0,%1,%2,%3}, {%4,%5,%6,%7}, {%8,%9}, {%0,%1,%2,%3};" \
        : "+f"((c)[0]), "+f"((c)[1]), "+f"((c)[2]), "+f"((c)[3]) \
        : "r"((a)[0]), "r"((a)[1]), "r"((a)[2]), "r"((a)[3]), "r"((b)[0]), "r"((b)[1]))

#define ASTRIDE_B  80                 // bytes per smem row (32 bf16 + 8 pad)

// ==================== STEP kernel smem layout (M-tile 64) ====================
#define S_AH     0
#define S_AL     5120                 // 64*80
#define S_BH     10240
#define S_BL     15360
#define S_STAGE  20480
#define S_NSTAGE 4
#define S_PRE    (S_NSTAGE * S_STAGE)      // 81920: pre tile 64x64 fp32 (16384 B)
#define S_C      (S_PRE + 16384)           // 98304: c tile 64x16 fp32 (4096 B)
#define S_MBAR   (S_C + 4096)              // 102400
#define S_SMEM   (S_MBAR + 64)             // 102464  -> 2 CTAs/SM

#define S_NCONS  256                  // 8 consumer warps
#define S_NPROD  64                   // 2 producer warps
#define S_NTOT   (S_NCONS + S_NPROD)  // 320

// ==================== PREGEMM smem layout (M-tile 128, 3 stages) ====================
#define P_AH     0
#define P_AL     10240                // 128*80
#define P_BH     20480
#define P_BL     25600
#define P_STAGE  30720
#define P_SMEM   (3 * P_STAGE)        // 92160 -> 2 CTAs/SM

// ==================== warp MMA core: one k32 chunk, warp tile 16x32, 3 split terms ====================
__device__ __forceinline__ void compute_chunk(uint32_t sb, uint32_t al_off, uint32_t bh_off,
                                              int wid, int lane, float acc[4][4]) {
    const int wm = (wid >> 1) * 16;
    const int wn = (wid & 1) * 32;
    const uint32_t a_row  = (uint32_t)(lane & 15);
    const uint32_t a_koff = (uint32_t)((lane >> 4) * 16);
    const uint32_t b_row  = (uint32_t)(((lane >> 4) << 3) + (lane & 7));
    const uint32_t b_koff = (uint32_t)(((lane >> 3) & 1) * 16);

#pragma unroll
    for (int ks = 0; ks < 2; ks++) {
        const uint32_t kb = (uint32_t)(ks * 32);
        uint32_t aH[4], aL[4], bH[4][2], bL[4][2];
        {
            uint32_t ad = sb + (wm + a_row) * ASTRIDE_B + kb + a_koff;
            LDSM4(aH[0], aH[1], aH[2], aH[3], ad);
            LDSM4(aL[0], aL[1], aL[2], aL[3], ad + al_off);
        }
#pragma unroll
        for (int p = 0; p < 2; p++) {
            uint32_t bd = sb + bh_off + (wn + p * 16 + b_row) * ASTRIDE_B + kb + b_koff;
            LDSM4(bH[2 * p][0], bH[2 * p][1], bH[2 * p + 1][0], bH[2 * p + 1][1], bd);
            LDSM4(bL[2 * p][0], bL[2 * p][1], bL[2 * p + 1][0], bL[2 * p + 1][1],
                  bd + (P_BL - P_BH));
        }
#pragma unroll
        for (int nt = 0; nt < 4; nt++) {
            MMA_BF16(acc[nt], aH, bH[nt]);
            MMA_BF16(acc[nt], aH, bL[nt]);
            MMA_BF16(acc[nt], aL, bH[nt]);
        }
    }
}

// ==================== init: permute + split weights, bias, h0 ====================
__global__ void permute_init_k(const float* __restrict__ Wi,
                               const float* __restrict__ Wh,
                               const float* __restrict__ bi,
                               const float* __restrict__ bh) {
    int stride = gridDim.x * blockDim.x;
    int tid0 = blockIdx.x * blockDim.x + threadIdx.x;
    for (int idx = tid0; idx < G_ * H_; idx += stride) {
        int jp = idx / H_, i = idx % H_;
        int gate = jp & 3, hh = jp >> 2;
        float w = Wh[(size_t)(gate * H_ + hh) * H_ + i];
        __nv_bfloat16 hi = __float2bfloat16_rn(w);
        g_Whp_hi[idx] = hi;
        g_Whp_lo[idx] = __float2bfloat16_rn(w - __bfloat162float(hi));
    }
    for (int idx = tid0; idx < G_ * I_; idx += stride) {
        int jp = idx / I_, i = idx % I_;
        int gate = jp & 3, hh = jp >> 2;
        float w = Wi[(size_t)(gate * H_ + hh) * I_ + i];
        __nv_bfloat16 hi = __float2bfloat16_rn(w);
        g_Wip_hi[idx] = hi;
        g_Wip_lo[idx] = __float2bfloat16_rn(w - __bfloat162float(hi));
    }
    for (int idx = tid0; idx < G_; idx += stride) {
        int gate = idx & 3, hh = idx >> 2;
        int j = gate * H_ + hh;
        g_biasp[idx] = bi[j] + bh[j];
    }
    for (int idx = tid0; idx < B_ * H_; idx += stride) {
        g_h_hi[0][idx] = __float2bfloat16_rn(0.0f);
        g_h_lo[0][idx] = __float2bfloat16_rn(0.0f);
    }
}

// ==================== split x into bf16 hi/lo ====================
__global__ void split_x_k(const float* __restrict__ x) {
    size_t n4 = (size_t)B_ * T_ * I_ / 4;
    size_t stride = (size_t)gridDim.x * blockDim.x;
    for (size_t i = blockIdx.x * blockDim.x + threadIdx.x; i < n4; i += stride) {
        float4 v = ((const float4*)x)[i];
        __nv_bfloat16 h0 = __float2bfloat16_rn(v.x);
        __nv_bfloat16 h1 = __float2bfloat16_rn(v.y);
        __nv_bfloat16 h2 = __float2bfloat16_rn(v.z);
        __nv_bfloat16 h3 = __float2bfloat16_rn(v.w);
        __nv_bfloat162* dhi = (__nv_bfloat162*)(g_x_hi + i * 4);
        __nv_bfloat162* dlo = (__nv_bfloat162*)(g_x_lo + i * 4);
        dhi[0] = __nv_bfloat162(h0, h1);
        dhi[1] = __nv_bfloat162(h2, h3);
        dlo[0] = __nv_bfloat162(__float2bfloat16_rn(v.x - __bfloat162float(h0)),
                                __float2bfloat16_rn(v.y - __bfloat162float(h1)));
        dlo[1] = __nv_bfloat162(__float2bfloat16_rn(v.z - __bfloat162float(h2)),
                                __float2bfloat16_rn(v.w - __bfloat162float(h3)));
    }
}

// ==================== pregemm: 3-stage ring, 2 CTAs/SM ====================
__device__ __forceinline__ void p_load_stage(uint32_t sb,
                                             const __nv_bfloat16* a_hi, const __nv_bfloat16* a_lo,
                                             const __nv_bfloat16* b_hi, const __nv_bfloat16* b_lo,
                                             int tid) {
    {
        int r = tid >> 2, u = tid & 3;        // 128 rows x 4 units
        uint32_t so = (uint32_t)(r * ASTRIDE_B + u * 16);
        CP16(sb + P_AH + so, a_hi + (size_t)r * I_ + u * 8);
        CP16(sb + P_AL + so, a_lo + (size_t)r * I_ + u * 8);
    }
    if (tid >= 256) {
        int t2 = tid - 256;
        int r = t2 >> 2, u = t2 & 3;          // 64 rows x 4 units
        uint32_t so = (uint32_t)(r * ASTRIDE_B + u * 16);
        CP16(sb + P_BH + so, b_hi + (size_t)r * I_ + u * 8);
        CP16(sb + P_BL + so, b_lo + (size_t)r * I_ + u * 8);
    }
}

__global__ void __launch_bounds__(512, 2) pregemm_k() {
    extern __shared__ char smem[];
    const uint32_t sm0 = smem_u32(smem);
    const int tid = threadIdx.x;
    const int wid = tid >> 5, lane = tid & 31;
    const int mb = blockIdx.x * 128;
    const int cb = blockIdx.y * 64;

    const __nv_bfloat16* a_hi = g_x_hi + (size_t)mb * I_;
    const __nv_bfloat16* a_lo = g_x_lo + (size_t)mb * I_;
    const __nv_bfloat16* b_hi = g_Wip_hi + (size_t)cb * I_;
    const __nv_bfloat16* b_lo = g_Wip_lo + (size_t)cb * I_;

    float acc[4][4] = {};

    // prologue: 2 stages in flight (3-stage ring, distance-2 prefetch)
#pragma unroll
    for (int s = 0; s < 2; s++) {
        p_load_stage(sm0 + s * P_STAGE, a_hi + s * 32, a_lo + s * 32,
                     b_hi + s * 32, b_lo + s * 32, tid);
        CP_COMMIT();
    }
#pragma unroll 1
    for (int ch = 0; ch < 16; ch++) {
        CP_WAIT1();
        __syncthreads();
        if (ch + 2 < 16) {
            int s = (ch + 2) % 3;
            p_load_stage(sm0 + s * P_STAGE, a_hi + (ch + 2) * 32, a_lo + (ch + 2) * 32,
                         b_hi + (ch + 2) * 32, b_lo + (ch + 2) * 32, tid);
        }
        CP_COMMIT();
        compute_chunk(sm0 + (ch % 3) * P_STAGE, P_AL - P_AH, P_BH, wid, lane, acc);
    }

    const int wm = (wid >> 1) * 16;
    const int wn = (wid & 1) * 32;
    const int qr = lane >> 2, qc = 2 * (lane & 3);
#pragma unroll
    for (int half = 0; half < 2; half++) {
        int r = wm + qr + half * 8;
        int m = mb + r;
        int b = m >> 9, tt = m & 511;
        float* preh = (tt < 256 ? g_pre0 : g_pre1);
        float* dst = preh + (size_t)(tt & 255) * B_ * G_ + (size_t)b * G_ + cb;
#pragma unroll
        for (int nt = 0; nt < 4; nt++) {
            int col = wn + nt * 8 + qc;
            dst[col]     = acc[nt][half * 2 + 0] + g_biasp[cb + col];
            dst[col + 1] = acc[nt][half * 2 + 1] + g_biasp[cb + col + 1];
        }
    }
}

// ==================== LSTM step: M=64 tile, warp-specialized, 2 CTAs/SM ====================
__device__ __forceinline__ float sigm(float v) { return 1.0f / (1.0f + expf(-v)); }

__global__ void __launch_bounds__(S_NTOT, 2) step_k(float* __restrict__ c, int t) {
    extern __shared__ char smem[];
    const uint32_t sm0 = smem_u32(smem);
    const int tid = threadIdx.x;
    const int wid = tid >> 5, lane = tid & 31;
    const int rb = blockIdx.x * 64;       // batch tile (M=64)
    const int cb = blockIdx.y * 64;       // j' tile
    const int hb = cb >> 2;

    const __nv_bfloat16* a_hi = g_h_hi[t & 1] + (size_t)rb * H_;
    const __nv_bfloat16* a_lo = g_h_lo[t & 1] + (size_t)rb * H_;
    const __nv_bfloat16* b_hi = g_Whp_hi + (size_t)cb * H_;
    const __nv_bfloat16* b_lo = g_Whp_lo + (size_t)cb * H_;
    __nv_bfloat16* __restrict__ hout_hi = g_h_hi[(t & 1) ^ 1];
    __nv_bfloat16* __restrict__ hout_lo = g_h_lo[(t & 1) ^ 1];

    const float* preh = (t < 256 ? g_pre0 : g_pre1);
    const float* prebase = preh + (size_t)(t & 255) * B_ * G_;

    const uint32_t mb_full = sm0 + S_MBAR;          // full[s] at +s*8
    const uint32_t mb_cons = sm0 + S_MBAR + 32;     // consumed[s] at +s*8

    if (tid == 0) {
#pragma unroll
        for (int s = 0; s < S_NSTAGE; s++) {
            MBARRIER_INIT(mb_full + s * 8, S_NPROD);  // 64 noinc async arrivals
            MBARRIER_INIT(mb_cons + s * 8, 8);        // 8 consumer-warp arrivals
        }
    }
    __syncthreads();

    float acc[4][4] = {};

    if (wid >= 8) {
        // ======== PRODUCER warps (2 warps, 64 threads) ========
        const int ptid = tid - S_NCONS;   // 0..63

        // prologue: epilogue operands (complete by wait_all below)
#pragma unroll
        for (int j = 0; j < 16; j++) {            // pre tile: 1024 x 16B units
            int u = ptid + j * S_NPROD;
            int r = u >> 4, q = u & 15;
            CP16(sm0 + S_PRE + (uint32_t)u * 16,
                 prebase + (size_t)(rb + r) * G_ + cb + q * 4);
        }
#pragma unroll
        for (int j = 0; j < 4; j++) {             // c tile: 256 x 16B units
            int u = ptid + j * S_NPROD;
            int r = u >> 2, q = u & 3;
            CP16(sm0 + S_C + (uint32_t)u * 16,
                 c + (size_t)(rb + r) * H_ + hb + q * 4);
        }

#pragma unroll 1
        for (int ch = 0; ch < 32; ch++) {
            const int s = ch & 3;
            const int round = ch >> 2;
            if (round >= 1) {
                MBARRIER_WAIT_PARITY(mb_cons + s * 8, (round - 1) & 1);
            }
            const uint32_t sb = sm0 + s * S_STAGE;
            const int k0 = ch * 32;
            // A hi/lo: 256 units each (64 rows x 4)
#pragma unroll
            for (int j = 0; j < 4; j++) {
                int u = ptid + j * S_NPROD;
                int r = u >> 2, c16 = u & 3;
                uint32_t so = (uint32_t)(r * ASTRIDE_B + c16 * 16);
                CP16(sb + S_AH + so, a_hi + (size_t)r * H_ + k0 + c16 * 8);
                CP16(sb + S_AL + so, a_lo + (size_t)r * H_ + k0 + c16 * 8);
            }
            // B hi/lo: 256 units each (64 rows x 4)
#pragma unroll
            for (int j = 0; j < 4; j++) {
                int u = ptid + j * S_NPROD;
                int r = u >> 2, c16 = u & 3;
                uint32_t so = (uint32_t)(r * ASTRIDE_B + c16 * 16);
                CP16(sb + S_BH + so, b_hi + (size_t)r * H_ + k0 + c16 * 8);
                CP16(sb + S_BL + so, b_lo + (size_t)r * H_ + k0 + c16 * 8);
            }
            CP_MBAR_ARRIVE_NOINC(mb_full + s * 8);
        }
        CP_WAIT_ALL();
    } else {
        // ======== CONSUMER warps (8 warps): free-running ========
#pragma unroll 1
        for (int ch = 0; ch < 32; ch++) {
            const int s = ch & 3;
            const int round = ch >> 2;
            MBARRIER_WAIT_PARITY(mb_full + s * 8, round & 1);
            compute_chunk(sm0 + s * S_STAGE, S_AL - S_AH, S_BH, wid, lane, acc);
            __syncwarp();
            if (lane == 0) MBARRIER_ARRIVE(mb_cons + s * 8);
        }
    }

    // ---- uniform convergence: ALL 320 threads hit the same barriers ----
    __syncthreads();   // stages dead; producers' epilogue cp.asyncs complete

    if (wid < 8) {
        float* Gs = (float*)smem;  // overlays stages 0/1 (dead)
        const int wm = (wid >> 1) * 16;
        const int wn = (wid & 1) * 32;
        const int qr = lane >> 2, qc = 2 * (lane & 3);
#pragma unroll
        for (int nt = 0; nt < 4; nt++) {
            int r0 = wm + qr;
            int cc = wn + nt * 8 + qc;
            Gs[r0 * 68 + cc]           = acc[nt][0];
            Gs[r0 * 68 + cc + 1]       = acc[nt][1];
            Gs[(r0 + 8) * 68 + cc]     = acc[nt][2];
            Gs[(r0 + 8) * 68 + cc + 1] = acc[nt][3];
        }
    }
    __syncthreads();

    // ---- activations + state update, all operands in smem (all 320 threads) ----
    {
        const float* Gs = (const float*)smem;
        const float4* PreS = (const float4*)(smem + S_PRE);   // [64][16] float4
        const float*  CS   = (const float*)(smem + S_C);      // [64][16]
        for (int it = tid; it < 64 * 16; it += S_NTOT) {
            int r = it >> 4, hh = it & 15;
            float4 g = *(const float4*)&Gs[r * 68 + hh * 4];
            float4 p = PreS[r * 16 + hh];
            float iv = sigm(g.x + p.x);
            float fv = sigm(g.y + p.y);
            float gv = tanhf(g.z + p.z);
            float ov = sigm(g.w + p.w);
            size_t idx = (size_t)(rb + r) * H_ + hb + hh;
            float cn = fv * CS[r * 16 + hh] + iv * gv;
            c[idx] = cn;
            float hn = ov * tanhf(cn);
            __nv_bfloat16 hi = __float2bfloat16_rn(hn);
            hout_hi[idx] = hi;
            hout_lo[idx] = __float2bfloat16_rn(hn - __bfloat162float(hi));
        }
    }
}

// ==================== launch ====================
extern "C" void kernel_launch(void* const* d_in, const int* in_sizes, int n_in,
                              void* d_out, int out_size) {
    const float* x  = (const float*)d_in[0];
    const float* Wi = (const float*)d_in[1];
    const float* Wh = (const float*)d_in[2];
    const float* bi = (const float*)d_in[3];
    const float* bh = (const float*)d_in[4];
    const float* c0 = (const float*)d_in[5];
    float* c = (float*)d_out;

    static bool attr_set = false;
    if (!attr_set) {
        cudaFuncSetAttribute(pregemm_k, cudaFuncAttributeMaxDynamicSharedMemorySize, P_SMEM);
        cudaFuncSetAttribute(step_k,    cudaFuncAttributeMaxDynamicSharedMemorySize, S_SMEM);
        attr_set = true;
    }

    cudaMemcpyAsync(c, c0, sizeof(float) * B_ * H_, cudaMemcpyDeviceToDevice);

    split_x_k<<<4096, 256>>>(x);
    permute_init_k<<<512, 256>>>(Wi, Wh, bi, bh);

    pregemm_k<<<dim3((B_ * T_) / 128, G_ / 64), 512, P_SMEM>>>();

    for (int t = 0; t < T_; t++) {
        step_k<<<dim3(B_ / 64, G_ / 64), S_NTOT, S_SMEM>>>(c, t);
    }
}

// round 15
// speedup vs baseline: 1.9576x; 1.6517x over previous
#include <cuda_runtime.h>
#include <cuda_fp16.h>
#include <cstdint>
#include <math.h>

#define B_ 256
#define T_ 512
#define I_ 512
#define H_ 1024
#define G_ 4096   // 4*H

// ==================== device scratch (no allocations allowed) ====================
__device__ float g_pre0[(size_t)256 * B_ * G_];
__device__ float g_pre1[(size_t)256 * B_ * G_];
__device__ __align__(128) __half g_x_h[(size_t)B_ * T_ * I_];
__device__ __align__(128) __half g_h_h[2][B_ * H_];
__device__ __align__(128) __half g_Wip_h[G_ * I_];
__device__ __align__(128) __half g_Whp_h[G_ * H_];
__device__ float g_biasp[G_];

// ==================== PTX helpers (plain sm_103 feature set) ====================
__device__ __forceinline__ uint32_t smem_u32(const void* p) {
    uint32_t a;
    asm("{ .reg .u64 t; cvta.to.shared.u64 t, %1; cvt.u32.u64 %0, t; }" : "=r"(a) : "l"(p));
    return a;
}
#define CP16(dst_u32, src_ptr) \
    asm volatile("cp.async.cg.shared.global [%0], [%1], 16;" :: "r"(dst_u32), "l"(src_ptr) : "memory")
#define CP_COMMIT() asm volatile("cp.async.commit_group;" ::: "memory")
#define CP_WAIT1()  asm volatile("cp.async.wait_group 1;" ::: "memory")
#define CP_WAIT_ALL() asm volatile("cp.async.wait_all;" ::: "memory")
#define CP_MBAR_ARRIVE_NOINC(addr) \
    asm volatile("cp.async.mbarrier.arrive.noinc.shared.b64 [%0];" :: "r"((uint32_t)(addr)) : "memory")
#define MBARRIER_INIT(addr, cnt) \
    asm volatile("mbarrier.init.shared.b64 [%0], %1;" :: "r"((uint32_t)(addr)), "r"((uint32_t)(cnt)) : "memory")
#define MBARRIER_ARRIVE(addr) \
    asm volatile("mbarrier.arrive.shared.b64 _, [%0];" :: "r"((uint32_t)(addr)) : "memory")
#define MBARRIER_WAIT_PARITY(addr, par) do { \
    uint32_t _m = (uint32_t)(addr); uint32_t _p = (uint32_t)(par); uint32_t _d; \
    asm volatile("{\n\t.reg .pred p;\n\tmbarrier.try_wait.parity.acquire.cta.shared::cta.b64 p, [%1], %2;\n\tselp.b32 %0, 1, 0, p;\n\t}" \
        : "=r"(_d) : "r"(_m), "r"(_p) : "memory"); \
    if (!_d) { \
        asm volatile("{\n\t.reg .pred P1;\n\tWL_%=:\n\tmbarrier.try_wait.parity.acquire.cta.shared::cta.b64 P1, [%0], %1, 0x989680;\n\t@P1 bra.uni WD_%=;\n\tbra.uni WL_%=;\n\tWD_%=:\n\t}" \
            :: "r"(_m), "r"(_p) : "memory"); \
    } } while (0)
#define LDSM4(r0, r1, r2, r3, addr) \
    asm volatile("ldmatrix.sync.aligned.m8n8.x4.shared.b16 {%0,%1,%2,%3}, [%4];" \
        : "=r"(r0), "=r"(r1), "=r"(r2), "=r"(r3) : "r"(addr))
#define MMA_FP16(c, a, b) \
    asm volatile("mma.sync.aligned.m16n8k16.row.col.f32.f16.f16.f32 " \
        "{%0,%1,%2,%3}, {%4,%5,%6,%7}, {%8,%9}, {%0,%1,%2,%3};" \
        : "+f"((c)[0]), "+f"((c)[1]), "+f"((c)[2]), "+f"((c)[3]) \
        : "r"((a)[0]), "r"((a)[1]), "r"((a)[2]), "r"((a)[3]), "r"((b)[0]), "r"((b)[1]))

#define ASTRIDE_B  80                 // bytes per smem row (32 fp16 = 64B + 16B pad)

// ==================== STEP kernel smem layout (M-tile 64, fp16 single-term) ====================
#define S_AH     0                    // A: 64 rows x 80B = 5120
#define S_BH     5120                 // B: 64 rows x 80B = 5120
#define S_STAGE  10240
#define S_NSTAGE 4
#define S_PRE    (S_NSTAGE * S_STAGE)      // 40960: pre tile 64x64 fp32 (16384 B)
#define S_C      (S_PRE + 16384)           // 57344: c tile 64x16 fp32 (4096 B)
#define S_MBAR   (S_C + 4096)              // 61440
#define S_SMEM   (S_MBAR + 64)             // 61504

#define S_NCONS  256                  // 8 consumer warps
#define S_NPROD  64                   // 2 producer warps
#define S_NTOT   (S_NCONS + S_NPROD)  // 320

// ==================== PREGEMM smem layout (M-tile 128, 3 stages) ====================
#define P_AH     0                    // A: 128 rows x 80B = 10240
#define P_BH     10240                // B: 64 rows x 80B = 5120
#define P_STAGE  15360
#define P_SMEM   (3 * P_STAGE)        // 46080

// ==================== warp MMA core: one k32 chunk, warp tile 16x32, fp16 single ====================
__device__ __forceinline__ void compute_chunk(uint32_t sb, uint32_t bh_off,
                                              int wid, int lane, float acc[4][4]) {
    const int wm = (wid >> 1) * 16;
    const int wn = (wid & 1) * 32;
    const uint32_t a_row  = (uint32_t)(lane & 15);
    const uint32_t a_koff = (uint32_t)((lane >> 4) * 16);
    const uint32_t b_row  = (uint32_t)(((lane >> 4) << 3) + (lane & 7));
    const uint32_t b_koff = (uint32_t)(((lane >> 3) & 1) * 16);

#pragma unroll
    for (int ks = 0; ks < 2; ks++) {
        const uint32_t kb = (uint32_t)(ks * 32);   // k16 of fp16 = 32 bytes
        uint32_t aH[4], bH[4][2];
        {
            uint32_t ad = sb + (wm + a_row) * ASTRIDE_B + kb + a_koff;
            LDSM4(aH[0], aH[1], aH[2], aH[3], ad);
        }
#pragma unroll
        for (int p = 0; p < 2; p++) {
            uint32_t bd = sb + bh_off + (wn + p * 16 + b_row) * ASTRIDE_B + kb + b_koff;
            LDSM4(bH[2 * p][0], bH[2 * p][1], bH[2 * p + 1][0], bH[2 * p + 1][1], bd);
        }
#pragma unroll
        for (int nt = 0; nt < 4; nt++)
            MMA_FP16(acc[nt], aH, bH[nt]);
    }
}

// ==================== init: permute weights -> fp16, bias, h0 ====================
__global__ void permute_init_k(const float* __restrict__ Wi,
                               const float* __restrict__ Wh,
                               const float* __restrict__ bi,
                               const float* __restrict__ bh) {
    int stride = gridDim.x * blockDim.x;
    int tid0 = blockIdx.x * blockDim.x + threadIdx.x;
    for (int idx = tid0; idx < G_ * H_; idx += stride) {
        int jp = idx / H_, i = idx % H_;
        int gate = jp & 3, hh = jp >> 2;
        g_Whp_h[idx] = __float2half_rn(Wh[(size_t)(gate * H_ + hh) * H_ + i]);
    }
    for (int idx = tid0; idx < G_ * I_; idx += stride) {
        int jp = idx / I_, i = idx % I_;
        int gate = jp & 3, hh = jp >> 2;
        g_Wip_h[idx] = __float2half_rn(Wi[(size_t)(gate * H_ + hh) * I_ + i]);
    }
    for (int idx = tid0; idx < G_; idx += stride) {
        int gate = idx & 3, hh = idx >> 2;
        int j = gate * H_ + hh;
        g_biasp[idx] = bi[j] + bh[j];
    }
    for (int idx = tid0; idx < B_ * H_; idx += stride) {
        g_h_h[0][idx] = __float2half_rn(0.0f);
    }
}

// ==================== convert x -> fp16 ====================
__global__ void cvt_x_k(const float* __restrict__ x) {
    size_t n4 = (size_t)B_ * T_ * I_ / 4;
    size_t stride = (size_t)gridDim.x * blockDim.x;
    for (size_t i = blockIdx.x * blockDim.x + threadIdx.x; i < n4; i += stride) {
        float4 v = ((const float4*)x)[i];
        __half2* d = (__half2*)(g_x_h + i * 4);
        d[0] = __floats2half2_rn(v.x, v.y);
        d[1] = __floats2half2_rn(v.z, v.w);
    }
}

// ==================== pregemm: 3-stage ring, fp16 single-term ====================
__device__ __forceinline__ void p_load_stage(uint32_t sb,
                                             const __half* a_h, const __half* b_h, int tid) {
    {
        int r = tid >> 2, u = tid & 3;        // 128 rows x 4 units(16B) = 512
        uint32_t so = (uint32_t)(r * ASTRIDE_B + u * 16);
        CP16(sb + P_AH + so, a_h + (size_t)r * I_ + u * 8);
    }
    if (tid >= 256) {
        int t2 = tid - 256;
        int r = t2 >> 2, u = t2 & 3;          // 64 rows x 4 units
        uint32_t so = (uint32_t)(r * ASTRIDE_B + u * 16);
        CP16(sb + P_BH + so, b_h + (size_t)r * I_ + u * 8);
    }
}

__global__ void __launch_bounds__(512, 2) pregemm_k() {
    extern __shared__ char smem[];
    const uint32_t sm0 = smem_u32(smem);
    const int tid = threadIdx.x;
    const int wid = tid >> 5, lane = tid & 31;
    const int mb = blockIdx.x * 128;
    const int cb = blockIdx.y * 64;

    const __half* a_h = g_x_h + (size_t)mb * I_;
    const __half* b_h = g_Wip_h + (size_t)cb * I_;

    float acc[4][4] = {};

#pragma unroll
    for (int s = 0; s < 2; s++) {
        p_load_stage(sm0 + s * P_STAGE, a_h + s * 32, b_h + s * 32, tid);
        CP_COMMIT();
    }
#pragma unroll 1
    for (int ch = 0; ch < 16; ch++) {
        CP_WAIT1();
        __syncthreads();
        if (ch + 2 < 16) {
            int s = (ch + 2) % 3;
            p_load_stage(sm0 + s * P_STAGE, a_h + (ch + 2) * 32, b_h + (ch + 2) * 32, tid);
        }
        CP_COMMIT();
        compute_chunk(sm0 + (ch % 3) * P_STAGE, P_BH, wid, lane, acc);
    }

    const int wm = (wid >> 1) * 16;
    const int wn = (wid & 1) * 32;
    const int qr = lane >> 2, qc = 2 * (lane & 3);
#pragma unroll
    for (int half = 0; half < 2; half++) {
        int r = wm + qr + half * 8;
        int m = mb + r;
        int b = m >> 9, tt = m & 511;
        float* preh = (tt < 256 ? g_pre0 : g_pre1);
        float* dst = preh + (size_t)(tt & 255) * B_ * G_ + (size_t)b * G_ + cb;
#pragma unroll
        for (int nt = 0; nt < 4; nt++) {
            int col = wn + nt * 8 + qc;
            dst[col]     = acc[nt][half * 2 + 0] + g_biasp[cb + col];
            dst[col + 1] = acc[nt][half * 2 + 1] + g_biasp[cb + col + 1];
        }
    }
}

// ==================== LSTM step: M=64 tile, warp-specialized, fp16 single-term ====================
__device__ __forceinline__ float sigm(float v) { return 1.0f / (1.0f + expf(-v)); }

__global__ void __launch_bounds__(S_NTOT, 2) step_k(float* __restrict__ c, int t) {
    extern __shared__ char smem[];
    const uint32_t sm0 = smem_u32(smem);
    const int tid = threadIdx.x;
    const int wid = tid >> 5, lane = tid & 31;
    const int rb = blockIdx.x * 64;       // batch tile (M=64)
    const int cb = blockIdx.y * 64;       // j' tile
    const int hb = cb >> 2;

    const __half* a_h = g_h_h[t & 1] + (size_t)rb * H_;
    const __half* b_h = g_Whp_h + (size_t)cb * H_;
    __half* __restrict__ hout = g_h_h[(t & 1) ^ 1];

    const float* preh = (t < 256 ? g_pre0 : g_pre1);
    const float* prebase = preh + (size_t)(t & 255) * B_ * G_;

    const uint32_t mb_full = sm0 + S_MBAR;          // full[s] at +s*8
    const uint32_t mb_cons = sm0 + S_MBAR + 32;     // consumed[s] at +s*8

    if (tid == 0) {
#pragma unroll
        for (int s = 0; s < S_NSTAGE; s++) {
            MBARRIER_INIT(mb_full + s * 8, S_NPROD);  // 64 noinc async arrivals
            MBARRIER_INIT(mb_cons + s * 8, 8);        // 8 consumer-warp arrivals
        }
    }
    __syncthreads();

    float acc[4][4] = {};

    if (wid >= 8) {
        // ======== PRODUCER warps (2 warps, 64 threads) ========
        const int ptid = tid - S_NCONS;   // 0..63

        // prologue: epilogue operands (complete by wait_all below)
#pragma unroll
        for (int j = 0; j < 16; j++) {            // pre tile: 1024 x 16B units
            int u = ptid + j * S_NPROD;
            int r = u >> 4, q = u & 15;
            CP16(sm0 + S_PRE + (uint32_t)u * 16,
                 prebase + (size_t)(rb + r) * G_ + cb + q * 4);
        }
#pragma unroll
        for (int j = 0; j < 4; j++) {             // c tile: 256 x 16B units
            int u = ptid + j * S_NPROD;
            int r = u >> 2, q = u & 3;
            CP16(sm0 + S_C + (uint32_t)u * 16,
                 c + (size_t)(rb + r) * H_ + hb + q * 4);
        }

#pragma unroll 1
        for (int ch = 0; ch < 32; ch++) {
            const int s = ch & 3;
            const int round = ch >> 2;
            if (round >= 1) {
                MBARRIER_WAIT_PARITY(mb_cons + s * 8, (round - 1) & 1);
            }
            const uint32_t sb = sm0 + s * S_STAGE;
            const int k0 = ch * 32;
            // A: 256 units (64 rows x 4x16B)
#pragma unroll
            for (int j = 0; j < 4; j++) {
                int u = ptid + j * S_NPROD;
                int r = u >> 2, c16 = u & 3;
                uint32_t so = (uint32_t)(r * ASTRIDE_B + c16 * 16);
                CP16(sb + S_AH + so, a_h + (size_t)r * H_ + k0 + c16 * 8);
            }
            // B: 256 units (64 rows x 4x16B)
#pragma unroll
            for (int j = 0; j < 4; j++) {
                int u = ptid + j * S_NPROD;
                int r = u >> 2, c16 = u & 3;
                uint32_t so = (uint32_t)(r * ASTRIDE_B + c16 * 16);
                CP16(sb + S_BH + so, b_h + (size_t)r * H_ + k0 + c16 * 8);
            }
            CP_MBAR_ARRIVE_NOINC(mb_full + s * 8);
        }
        CP_WAIT_ALL();
    } else {
        // ======== CONSUMER warps (8 warps): free-running ========
#pragma unroll 1
        for (int ch = 0; ch < 32; ch++) {
            const int s = ch & 3;
            const int round = ch >> 2;
            MBARRIER_WAIT_PARITY(mb_full + s * 8, round & 1);
            compute_chunk(sm0 + s * S_STAGE, S_BH, wid, lane, acc);
            __syncwarp();
            if (lane == 0) MBARRIER_ARRIVE(mb_cons + s * 8);
        }
    }

    // ---- uniform convergence: ALL 320 threads hit the same barriers ----
    __syncthreads();   // stages dead; producers' epilogue cp.asyncs complete

    if (wid < 8) {
        float* Gs = (float*)smem;  // overlays stages (dead)
        const int wm = (wid >> 1) * 16;
        const int wn = (wid & 1) * 32;
        const int qr = lane >> 2, qc = 2 * (lane & 3);
#pragma unroll
        for (int nt = 0; nt < 4; nt++) {
            int r0 = wm + qr;
            int cc = wn + nt * 8 + qc;
            Gs[r0 * 68 + cc]           = acc[nt][0];
            Gs[r0 * 68 + cc + 1]       = acc[nt][1];
            Gs[(r0 + 8) * 68 + cc]     = acc[nt][2];
            Gs[(r0 + 8) * 68 + cc + 1] = acc[nt][3];
        }
    }
    __syncthreads();

    // ---- activations + state update, all operands in smem (all 320 threads) ----
    {
        const float* Gs = (const float*)smem;
        const float4* PreS = (const float4*)(smem + S_PRE);   // [64][16] float4
        const float*  CS   = (const float*)(smem + S_C);      // [64][16]
        for (int it = tid; it < 64 * 16; it += S_NTOT) {
            int r = it >> 4, hh = it & 15;
            float4 g = *(const float4*)&Gs[r * 68 + hh * 4];
            float4 p = PreS[r * 16 + hh];
            float iv = sigm(g.x + p.x);
            float fv = sigm(g.y + p.y);
            float gv = tanhf(g.z + p.z);
            float ov = sigm(g.w + p.w);
            size_t idx = (size_t)(rb + r) * H_ + hb + hh;
            float cn = fv * CS[r * 16 + hh] + iv * gv;
            c[idx] = cn;
            hout[idx] = __float2half_rn(ov * tanhf(cn));
        }
    }
}

// ==================== launch ====================
extern "C" void kernel_launch(void* const* d_in, const int* in_sizes, int n_in,
                              void* d_out, int out_size) {
    const float* x  = (const float*)d_in[0];
    const float* Wi = (const float*)d_in[1];
    const float* Wh = (const float*)d_in[2];
    const float* bi = (const float*)d_in[3];
    const float* bh = (const float*)d_in[4];
    const float* c0 = (const float*)d_in[5];
    float* c = (float*)d_out;

    static bool attr_set = false;
    if (!attr_set) {
        cudaFuncSetAttribute(pregemm_k, cudaFuncAttributeMaxDynamicSharedMemorySize, P_SMEM);
        cudaFuncSetAttribute(step_k,    cudaFuncAttributeMaxDynamicSharedMemorySize, S_SMEM);
        attr_set = true;
    }

    cudaMemcpyAsync(c, c0, sizeof(float) * B_ * H_, cudaMemcpyDeviceToDevice);

    cvt_x_k<<<4096, 256>>>(x);
    permute_init_k<<<512, 256>>>(Wi, Wh, bi, bh);

    pregemm_k<<<dim3((B_ * T_) / 128, G_ / 64), 512, P_SMEM>>>();

    for (int t = 0; t < T_; t++) {
        step_k<<<dim3(B_ / 64, G_ / 64), S_NTOT, S_SMEM>>>(c, t);
    }
}

// round 16
// speedup vs baseline: 2.0800x; 1.0625x over previous
#include <cuda_runtime.h>
#include <cuda_fp16.h>
#include <cstdint>
#include <math.h>

#define B_ 256
#define T_ 512
#define I_ 512
#define H_ 1024
#define G_ 4096   // 4*H
#define NBLK 128  // persistent grid size

// ==================== device scratch (no allocations allowed) ====================
__device__ float g_pre0[(size_t)256 * B_ * G_];
__device__ float g_pre1[(size_t)256 * B_ * G_];
__device__ __align__(128) __half g_x_h[(size_t)B_ * T_ * I_];
__device__ __align__(128) __half g_h_h[2][B_ * H_];
__device__ __align__(128) __half g_Wip_h[G_ * I_];
__device__ __align__(128) __half g_Whp_h[G_ * H_];
__device__ float g_biasp[G_];
__device__ unsigned g_bar[T_];          // per-step grid-barrier counters

// ==================== PTX helpers (plain sm_103 feature set) ====================
__device__ __forceinline__ uint32_t smem_u32(const void* p) {
    uint32_t a;
    asm("{ .reg .u64 t; cvta.to.shared.u64 t, %1; cvt.u32.u64 %0, t; }" : "=r"(a) : "l"(p));
    return a;
}
#define CP16(dst_u32, src_ptr) \
    asm volatile("cp.async.cg.shared.global [%0], [%1], 16;" :: "r"(dst_u32), "l"(src_ptr) : "memory")
#define CP_COMMIT() asm volatile("cp.async.commit_group;" ::: "memory")
#define CP_WAIT1()  asm volatile("cp.async.wait_group 1;" ::: "memory")
#define CP_WAIT_ALL() asm volatile("cp.async.wait_all;" ::: "memory")
#define CP_MBAR_ARRIVE_NOINC(addr) \
    asm volatile("cp.async.mbarrier.arrive.noinc.shared.b64 [%0];" :: "r"((uint32_t)(addr)) : "memory")
#define MBARRIER_INIT(addr, cnt) \
    asm volatile("mbarrier.init.shared.b64 [%0], %1;" :: "r"((uint32_t)(addr)), "r"((uint32_t)(cnt)) : "memory")
#define MBARRIER_ARRIVE(addr) \
    asm volatile("mbarrier.arrive.shared.b64 _, [%0];" :: "r"((uint32_t)(addr)) : "memory")
#define MBARRIER_WAIT_PARITY(addr, par) do { \
    uint32_t _m = (uint32_t)(addr); uint32_t _p = (uint32_t)(par); uint32_t _d; \
    asm volatile("{\n\t.reg .pred p;\n\tmbarrier.try_wait.parity.acquire.cta.shared::cta.b64 p, [%1], %2;\n\tselp.b32 %0, 1, 0, p;\n\t}" \
        : "=r"(_d) : "r"(_m), "r"(_p) : "memory"); \
    if (!_d) { \
        asm volatile("{\n\t.reg .pred P1;\n\tWL_%=:\n\tmbarrier.try_wait.parity.acquire.cta.shared::cta.b64 P1, [%0], %1, 0x989680;\n\t@P1 bra.uni WD_%=;\n\tbra.uni WL_%=;\n\tWD_%=:\n\t}" \
            :: "r"(_m), "r"(_p) : "memory"); \
    } } while (0)
#define LDSM4(r0, r1, r2, r3, addr) \
    asm volatile("ldmatrix.sync.aligned.m8n8.x4.shared.b16 {%0,%1,%2,%3}, [%4];" \
        : "=r"(r0), "=r"(r1), "=r"(r2), "=r"(r3) : "r"(addr))
#define MMA_FP16(c, a, b) \
    asm volatile("mma.sync.aligned.m16n8k16.row.col.f32.f16.f16.f32 " \
        "{%0,%1,%2,%3}, {%4,%5,%6,%7}, {%8,%9}, {%0,%1,%2,%3};" \
        : "+f"((c)[0]), "+f"((c)[1]), "+f"((c)[2]), "+f"((c)[3]) \
        : "r"((a)[0]), "r"((a)[1]), "r"((a)[2]), "r"((a)[3]), "r"((b)[0]), "r"((b)[1]))

#define ASTRIDE_B  80                 // bytes per smem row (32 fp16 + 16B pad)

// ==================== PERSISTENT step kernel smem layout (M=128) ====================
#define S_AH     0                    // A: 128 rows x 80B = 10240
#define S_BH     10240                // B: 64 rows x 80B = 5120
#define S_STAGE  15360
#define S_NSTAGE 4
#define S_PRE    (S_NSTAGE * S_STAGE)      // 61440: pre tile 128x64 fp32 (32768 B)
#define S_C      (S_PRE + 32768)           // 94208: c tile 128x16 fp32 (8192 B)
#define S_MBAR   (S_C + 8192)              // 102400
#define S_SMEM   (S_MBAR + 64)             // 102464 (<=228KB -> guaranteed resident)

#define S_NCONS  512                  // 16 consumer warps
#define S_NPROD  128                  // 4 producer warps
#define S_NTOT   (S_NCONS + S_NPROD)  // 640

// ==================== PREGEMM smem layout (unchanged from round 15) ====================
#define P_AH     0
#define P_BH     10240
#define P_STAGE  15360
#define P_SMEM   (3 * P_STAGE)        // 46080

// ==================== warp MMA core: one k32 chunk, warp tile 16x32, fp16 ====================
__device__ __forceinline__ void compute_chunk(uint32_t sb, uint32_t bh_off,
                                              int wid, int lane, float acc[4][4]) {
    const int wm = (wid >> 1) * 16;
    const int wn = (wid & 1) * 32;
    const uint32_t a_row  = (uint32_t)(lane & 15);
    const uint32_t a_koff = (uint32_t)((lane >> 4) * 16);
    const uint32_t b_row  = (uint32_t)(((lane >> 4) << 3) + (lane & 7));
    const uint32_t b_koff = (uint32_t)(((lane >> 3) & 1) * 16);

#pragma unroll
    for (int ks = 0; ks < 2; ks++) {
        const uint32_t kb = (uint32_t)(ks * 32);
        uint32_t aH[4], bH[4][2];
        {
            uint32_t ad = sb + (wm + a_row) * ASTRIDE_B + kb + a_koff;
            LDSM4(aH[0], aH[1], aH[2], aH[3], ad);
        }
#pragma unroll
        for (int p = 0; p < 2; p++) {
            uint32_t bd = sb + bh_off + (wn + p * 16 + b_row) * ASTRIDE_B + kb + b_koff;
            LDSM4(bH[2 * p][0], bH[2 * p][1], bH[2 * p + 1][0], bH[2 * p + 1][1], bd);
        }
#pragma unroll
        for (int nt = 0; nt < 4; nt++)
            MMA_FP16(acc[nt], aH, bH[nt]);
    }
}

// ==================== init kernels ====================
__global__ void permute_init_k(const float* __restrict__ Wi,
                               const float* __restrict__ Wh,
                               const float* __restrict__ bi,
                               const float* __restrict__ bh) {
    int stride = gridDim.x * blockDim.x;
    int tid0 = blockIdx.x * blockDim.x + threadIdx.x;
    for (int idx = tid0; idx < G_ * H_; idx += stride) {
        int jp = idx / H_, i = idx % H_;
        int gate = jp & 3, hh = jp >> 2;
        g_Whp_h[idx] = __float2half_rn(Wh[(size_t)(gate * H_ + hh) * H_ + i]);
    }
    for (int idx = tid0; idx < G_ * I_; idx += stride) {
        int jp = idx / I_, i = idx % I_;
        int gate = jp & 3, hh = jp >> 2;
        g_Wip_h[idx] = __float2half_rn(Wi[(size_t)(gate * H_ + hh) * I_ + i]);
    }
    for (int idx = tid0; idx < G_; idx += stride) {
        int gate = idx & 3, hh = idx >> 2;
        int j = gate * H_ + hh;
        g_biasp[idx] = bi[j] + bh[j];
    }
    for (int idx = tid0; idx < B_ * H_; idx += stride) {
        g_h_h[0][idx] = __float2half_rn(0.0f);
    }
    // reset grid-barrier counters (same launch, before persistent kernel)
    for (int idx = tid0; idx < T_; idx += stride) g_bar[idx] = 0u;
}

__global__ void cvt_x_k(const float* __restrict__ x) {
    size_t n4 = (size_t)B_ * T_ * I_ / 4;
    size_t stride = (size_t)gridDim.x * blockDim.x;
    for (size_t i = blockIdx.x * blockDim.x + threadIdx.x; i < n4; i += stride) {
        float4 v = ((const float4*)x)[i];
        __half2* d = (__half2*)(g_x_h + i * 4);
        d[0] = __floats2half2_rn(v.x, v.y);
        d[1] = __floats2half2_rn(v.z, v.w);
    }
}

// ==================== pregemm (unchanged from round 15) ====================
__device__ __forceinline__ void p_load_stage(uint32_t sb,
                                             const __half* a_h, const __half* b_h, int tid) {
    {
        int r = tid >> 2, u = tid & 3;
        uint32_t so = (uint32_t)(r * ASTRIDE_B + u * 16);
        CP16(sb + P_AH + so, a_h + (size_t)r * I_ + u * 8);
    }
    if (tid >= 256) {
        int t2 = tid - 256;
        int r = t2 >> 2, u = t2 & 3;
        uint32_t so = (uint32_t)(r * ASTRIDE_B + u * 16);
        CP16(sb + P_BH + so, b_h + (size_t)r * I_ + u * 8);
    }
}

__global__ void __launch_bounds__(512, 2) pregemm_k() {
    extern __shared__ char smem[];
    const uint32_t sm0 = smem_u32(smem);
    const int tid = threadIdx.x;
    const int wid = tid >> 5, lane = tid & 31;
    const int mb = blockIdx.x * 128;
    const int cb = blockIdx.y * 64;

    const __half* a_h = g_x_h + (size_t)mb * I_;
    const __half* b_h = g_Wip_h + (size_t)cb * I_;

    float acc[4][4] = {};

#pragma unroll
    for (int s = 0; s < 2; s++) {
        p_load_stage(sm0 + s * P_STAGE, a_h + s * 32, b_h + s * 32, tid);
        CP_COMMIT();
    }
#pragma unroll 1
    for (int ch = 0; ch < 16; ch++) {
        CP_WAIT1();
        __syncthreads();
        if (ch + 2 < 16) {
            int s = (ch + 2) % 3;
            p_load_stage(sm0 + s * P_STAGE, a_h + (ch + 2) * 32, b_h + (ch + 2) * 32, tid);
        }
        CP_COMMIT();
        compute_chunk(sm0 + (ch % 3) * P_STAGE, P_BH, wid, lane, acc);
    }

    const int wm = (wid >> 1) * 16;
    const int wn = (wid & 1) * 32;
    const int qr = lane >> 2, qc = 2 * (lane & 3);
#pragma unroll
    for (int half = 0; half < 2; half++) {
        int r = wm + qr + half * 8;
        int m = mb + r;
        int b = m >> 9, tt = m & 511;
        float* preh = (tt < 256 ? g_pre0 : g_pre1);
        float* dst = preh + (size_t)(tt & 255) * B_ * G_ + (size_t)b * G_ + cb;
#pragma unroll
        for (int nt = 0; nt < 4; nt++) {
            int col = wn + nt * 8 + qc;
            dst[col]     = acc[nt][half * 2 + 0] + g_biasp[cb + col];
            dst[col + 1] = acc[nt][half * 2 + 1] + g_biasp[cb + col + 1];
        }
    }
}

// ==================== PERSISTENT LSTM recurrence: all 512 steps in one kernel ====================
__device__ __forceinline__ float sigm(float v) { return 1.0f / (1.0f + expf(-v)); }

__global__ void __launch_bounds__(S_NTOT, 1) lstm_persist_k(float* __restrict__ c,
                                                            const float* __restrict__ c0) {
    extern __shared__ char smem[];
    const uint32_t sm0 = smem_u32(smem);
    const int tid = threadIdx.x;
    const int wid = tid >> 5, lane = tid & 31;
    const int rb = (blockIdx.x & 1) * 128;      // batch tile (M=128)
    const int cb = (blockIdx.x >> 1) * 64;      // j' tile
    const int hb = cb >> 2;

    const __half* b_h = g_Whp_h + (size_t)cb * H_;
    const uint32_t mb_full = sm0 + S_MBAR;
    const uint32_t mb_cons = sm0 + S_MBAR + 32;

    if (tid == 0) {
#pragma unroll
        for (int s = 0; s < S_NSTAGE; s++) {
            MBARRIER_INIT(mb_full + s * 8, S_NPROD);   // 128 noinc async arrivals
            MBARRIER_INIT(mb_cons + s * 8, 16);        // 16 consumer-warp arrivals
        }
    }
    // load c tile (resident in smem for the whole recurrence)
    if (tid < 512) {
        int r = tid >> 2, q = tid & 3;
        CP16(sm0 + S_C + (uint32_t)tid * 16, c0 + (size_t)(rb + r) * H_ + hb + q * 4);
    }
    CP_WAIT_ALL();
    __syncthreads();

    float* CS = (float*)(smem + S_C);          // [128][16]

#pragma unroll 1
    for (int t = 0; t < T_; t++) {
        const float* prebase = (t < 256 ? g_pre0 : g_pre1) + (size_t)(t & 255) * B_ * G_;
        const __half* a_h = g_h_h[t & 1] + (size_t)rb * H_;
        __half* __restrict__ hout = g_h_h[(t & 1) ^ 1];

        float acc[4][4] = {};

        if (wid >= 16) {
            // ======== PRODUCER warps (4 warps, 128 threads) ========
            const int ptid = tid - S_NCONS;    // 0..127
#pragma unroll 1
            for (int ch = 0; ch < 32; ch++) {
                const int q = (t << 5) + ch;   // continuous chunk counter
                const int s = q & 3;
                if (q >= 4) MBARRIER_WAIT_PARITY(mb_cons + s * 8, ((q >> 2) - 1) & 1);
                const uint32_t sb = sm0 + s * S_STAGE;
                const int k0 = ch * 32;
                // A (h tile): 512 units (128 rows x 4x16B), 4/thread
#pragma unroll
                for (int j = 0; j < 4; j++) {
                    int u = ptid + j * S_NPROD;
                    int r = u >> 2, c16 = u & 3;
                    CP16(sb + S_AH + (uint32_t)(r * ASTRIDE_B + c16 * 16),
                         a_h + (size_t)r * H_ + k0 + c16 * 8);
                }
                // B (W tile): 256 units (64 rows x 4x16B), 2/thread
#pragma unroll
                for (int j = 0; j < 2; j++) {
                    int u = ptid + j * S_NPROD;
                    int r = u >> 2, c16 = u & 3;
                    CP16(sb + S_BH + (uint32_t)(r * ASTRIDE_B + c16 * 16),
                         b_h + (size_t)r * H_ + k0 + c16 * 8);
                }
                CP_MBAR_ARRIVE_NOINC(mb_full + s * 8);
                if (ch == 0) {
                    // pre tile for this step: 2048 units, 16/thread (covered by ch1 arrive)
#pragma unroll
                    for (int j = 0; j < 16; j++) {
                        int u = ptid + j * S_NPROD;
                        int r = u >> 4, qd = u & 15;
                        CP16(sm0 + S_PRE + (uint32_t)u * 16,
                             prebase + (size_t)(rb + r) * G_ + cb + qd * 4);
                    }
                }
            }
        } else {
            // ======== CONSUMER warps (16 warps): free-running ========
#pragma unroll 1
            for (int ch = 0; ch < 32; ch++) {
                const int q = (t << 5) + ch;
                const int s = q & 3;
                MBARRIER_WAIT_PARITY(mb_full + s * 8, (q >> 2) & 1);
                compute_chunk(sm0 + s * S_STAGE, S_BH, wid, lane, acc);
                __syncwarp();
                if (lane == 0) MBARRIER_ARRIVE(mb_cons + s * 8);
            }
        }

        // ---- uniform convergence ----
        __syncthreads();                       // stages consumed; pre arrived

        if (wid < 16) {
            float* Gs = (float*)smem;          // overlays stages (dead until next step)
            const int wm = (wid >> 1) * 16;
            const int wn = (wid & 1) * 32;
            const int qr = lane >> 2, qc = 2 * (lane & 3);
#pragma unroll
            for (int nt = 0; nt < 4; nt++) {
                int r0 = wm + qr;
                int cc = wn + nt * 8 + qc;
                Gs[r0 * 68 + cc]           = acc[nt][0];
                Gs[r0 * 68 + cc + 1]       = acc[nt][1];
                Gs[(r0 + 8) * 68 + cc]     = acc[nt][2];
                Gs[(r0 + 8) * 68 + cc + 1] = acc[nt][3];
            }
        }
        __syncthreads();

        // ---- pointwise: c in smem, h -> gmem fp16 (all 640 threads) ----
        {
            const float* Gs = (const float*)smem;
            const float4* PreS = (const float4*)(smem + S_PRE);
            for (int it = tid; it < 128 * 16; it += S_NTOT) {
                int r = it >> 4, hh = it & 15;
                float4 g = *(const float4*)&Gs[r * 68 + hh * 4];
                float4 p = PreS[r * 16 + hh];
                float iv = sigm(g.x + p.x);
                float fv = sigm(g.y + p.y);
                float gv = tanhf(g.z + p.z);
                float ov = sigm(g.w + p.w);
                float cn = fv * CS[it] + iv * gv;
                CS[it] = cn;
                hout[(size_t)(rb + r) * H_ + hb + hh] = __float2half_rn(ov * tanhf(cn));
            }
        }

        // ---- grid-wide barrier (all 128 CTAs guaranteed co-resident) ----
        __threadfence();
        __syncthreads();
        if (tid == 0) {
            atomicAdd(&g_bar[t], 1u);
            while (*(volatile unsigned*)&g_bar[t] < NBLK) {}
            __threadfence();
        }
        __syncthreads();
    }

    // ---- final: write resident c tile to output ----
    for (int it = tid; it < 128 * 16; it += S_NTOT) {
        int r = it >> 4, hh = it & 15;
        c[(size_t)(rb + r) * H_ + hb + hh] = CS[it];
    }
}

// ==================== launch ====================
extern "C" void kernel_launch(void* const* d_in, const int* in_sizes, int n_in,
                              void* d_out, int out_size) {
    const float* x  = (const float*)d_in[0];
    const float* Wi = (const float*)d_in[1];
    const float* Wh = (const float*)d_in[2];
    const float* bi = (const float*)d_in[3];
    const float* bh = (const float*)d_in[4];
    const float* c0 = (const float*)d_in[5];
    float* c = (float*)d_out;

    static bool attr_set = false;
    if (!attr_set) {
        cudaFuncSetAttribute(pregemm_k, cudaFuncAttributeMaxDynamicSharedMemorySize, P_SMEM);
        cudaFuncSetAttribute(lstm_persist_k, cudaFuncAttributeMaxDynamicSharedMemorySize, S_SMEM);
        attr_set = true;
    }

    cvt_x_k<<<4096, 256>>>(x);
    permute_init_k<<<512, 256>>>(Wi, Wh, bi, bh);   // also resets g_bar

    pregemm_k<<<dim3((B_ * T_) / 128, G_ / 64), 512, P_SMEM>>>();

    lstm_persist_k<<<NBLK, S_NTOT, S_SMEM>>>(c, c0);
}

// round 17
// speedup vs baseline: 2.1789x; 1.0476x over previous
#include <cuda_runtime.h>
#include <cuda_fp16.h>
#include <cstdint>
#include <math.h>

#define B_ 256
#define T_ 512
#define I_ 512
#define H_ 1024
#define G_ 4096   // 4*H
#define NBLK 128  // persistent grid size

// ==================== device scratch (no allocations allowed) ====================
__device__ float g_pre0[(size_t)256 * B_ * G_];
__device__ float g_pre1[(size_t)256 * B_ * G_];
__device__ __align__(128) __half g_x_h[(size_t)B_ * T_ * I_];
__device__ __align__(128) __half g_h_h[2][B_ * H_];
__device__ __align__(128) __half g_Wip_h[G_ * I_];
__device__ __align__(128) __half g_Whp_h[G_ * H_];
__device__ float g_biasp[G_];
__device__ unsigned g_bar[T_];          // per-step grid-barrier counters

// ==================== PTX helpers (plain sm_103 feature set) ====================
__device__ __forceinline__ uint32_t smem_u32(const void* p) {
    uint32_t a;
    asm("{ .reg .u64 t; cvta.to.shared.u64 t, %1; cvt.u32.u64 %0, t; }" : "=r"(a) : "l"(p));
    return a;
}
#define CP16(dst_u32, src_ptr) \
    asm volatile("cp.async.cg.shared.global [%0], [%1], 16;" :: "r"(dst_u32), "l"(src_ptr) : "memory")
#define CP_COMMIT() asm volatile("cp.async.commit_group;" ::: "memory")
#define CP_WAIT1()  asm volatile("cp.async.wait_group 1;" ::: "memory")
#define CP_WAIT_ALL() asm volatile("cp.async.wait_all;" ::: "memory")
#define CP_MBAR_ARRIVE_NOINC(addr) \
    asm volatile("cp.async.mbarrier.arrive.noinc.shared.b64 [%0];" :: "r"((uint32_t)(addr)) : "memory")
#define MBARRIER_INIT(addr, cnt) \
    asm volatile("mbarrier.init.shared.b64 [%0], %1;" :: "r"((uint32_t)(addr)), "r"((uint32_t)(cnt)) : "memory")
#define MBARRIER_ARRIVE(addr) \
    asm volatile("mbarrier.arrive.shared.b64 _, [%0];" :: "r"((uint32_t)(addr)) : "memory")
#define MBARRIER_WAIT_PARITY(addr, par) do { \
    uint32_t _m = (uint32_t)(addr); uint32_t _p = (uint32_t)(par); uint32_t _d; \
    asm volatile("{\n\t.reg .pred p;\n\tmbarrier.try_wait.parity.acquire.cta.shared::cta.b64 p, [%1], %2;\n\tselp.b32 %0, 1, 0, p;\n\t}" \
        : "=r"(_d) : "r"(_m), "r"(_p) : "memory"); \
    if (!_d) { \
        asm volatile("{\n\t.reg .pred P1;\n\tWL_%=:\n\tmbarrier.try_wait.parity.acquire.cta.shared::cta.b64 P1, [%0], %1, 0x989680;\n\t@P1 bra.uni WD_%=;\n\tbra.uni WL_%=;\n\tWD_%=:\n\t}" \
            :: "r"(_m), "r"(_p) : "memory"); \
    } } while (0)
#define LDSM4(r0, r1, r2, r3, addr) \
    asm volatile("ldmatrix.sync.aligned.m8n8.x4.shared.b16 {%0,%1,%2,%3}, [%4];" \
        : "=r"(r0), "=r"(r1), "=r"(r2), "=r"(r3) : "r"(addr))
#define MMA_FP16(c, a, b) \
    asm volatile("mma.sync.aligned.m16n8k16.row.col.f32.f16.f16.f32 " \
        "{%0,%1,%2,%3}, {%4,%5,%6,%7}, {%8,%9}, {%0,%1,%2,%3};" \
        : "+f"((c)[0]), "+f"((c)[1]), "+f"((c)[2]), "+f"((c)[3]) \
        : "r"((a)[0]), "r"((a)[1]), "r"((a)[2]), "r"((a)[3]), "r"((b)[0]), "r"((b)[1]))

#define ASTRIDE_B  80                 // bytes per smem row (32 fp16 + 16B pad)

// ==================== PERSISTENT kernel smem layout (M=128, W-resident) ====================
#define S_W      0                    // W resident: 32 chunks x 64 rows x 64B = 131072
#define S_STAGEA 131072               // A stages: 4 x (128 x 80B) = 40960
#define S_ASTG   10240
#define S_NSTAGE 4
#define S_PRE    (S_STAGEA + S_NSTAGE * S_ASTG)   // 172032: pre tile 128x64 fp32 (32768)
#define S_MBAR   (S_PRE + 32768)                  // 204800: full[4], cons[4], pre_mb
#define S_SMEM   (S_MBAR + 128)                   // 204928 (< 227KB, 1 CTA/SM)

#define S_NCONS  512                  // 16 consumer warps
#define S_NPROD  128                  // 4 producer warps
#define S_NTOT   (S_NCONS + S_NPROD)  // 640

// ==================== PREGEMM smem layout (unchanged) ====================
#define P_AH     0
#define P_BH     10240
#define P_STAGE  15360
#define P_SMEM   (3 * P_STAGE)        // 46080

// ==================== warp MMA core (stage A + resident W) ====================
__device__ __forceinline__ void compute_chunk_w(uint32_t sa, uint32_t swch,
                                                int wid, int lane, float acc[4][4]) {
    const int wm = (wid >> 1) * 16;
    const int wn = (wid & 1) * 32;
    const uint32_t a_row  = (uint32_t)(lane & 15);
    const uint32_t a_koff = (uint32_t)((lane >> 4) * 16);
    const int b_row = ((lane >> 4) << 3) + (lane & 7);       // 0..15
    const int b_u0  = (lane >> 3) & 1;                       // unit low bit

#pragma unroll
    for (int ks = 0; ks < 2; ks++) {
        uint32_t aH[4], bH[4][2];
        {
            uint32_t ad = sa + (wm + a_row) * ASTRIDE_B + (uint32_t)(ks * 32) + a_koff;
            LDSM4(aH[0], aH[1], aH[2], aH[3], ad);
        }
#pragma unroll
        for (int p = 0; p < 2; p++) {
            int row = wn + p * 16 + b_row;
            int u = ks * 2 + b_u0;
            uint32_t bd = swch + (uint32_t)(row * 64 + ((u ^ ((row >> 1) & 3)) << 4));
            LDSM4(bH[2 * p][0], bH[2 * p][1], bH[2 * p + 1][0], bH[2 * p + 1][1], bd);
        }
#pragma unroll
        for (int nt = 0; nt < 4; nt++)
            MMA_FP16(acc[nt], aH, bH[nt]);
    }
}

// pregemm variant: A + B both from padded stages
__device__ __forceinline__ void compute_chunk(uint32_t sb, uint32_t bh_off,
                                              int wid, int lane, float acc[4][4]) {
    const int wm = (wid >> 1) * 16;
    const int wn = (wid & 1) * 32;
    const uint32_t a_row  = (uint32_t)(lane & 15);
    const uint32_t a_koff = (uint32_t)((lane >> 4) * 16);
    const uint32_t b_row  = (uint32_t)(((lane >> 4) << 3) + (lane & 7));
    const uint32_t b_koff = (uint32_t)(((lane >> 3) & 1) * 16);

#pragma unroll
    for (int ks = 0; ks < 2; ks++) {
        const uint32_t kb = (uint32_t)(ks * 32);
        uint32_t aH[4], bH[4][2];
        {
            uint32_t ad = sb + (wm + a_row) * ASTRIDE_B + kb + a_koff;
            LDSM4(aH[0], aH[1], aH[2], aH[3], ad);
        }
#pragma unroll
        for (int p = 0; p < 2; p++) {
            uint32_t bd = sb + bh_off + (wn + p * 16 + b_row) * ASTRIDE_B + kb + b_koff;
            LDSM4(bH[2 * p][0], bH[2 * p][1], bH[2 * p + 1][0], bH[2 * p + 1][1], bd);
        }
#pragma unroll
        for (int nt = 0; nt < 4; nt++)
            MMA_FP16(acc[nt], aH, bH[nt]);
    }
}

// ==================== init kernels ====================
__global__ void permute_init_k(const float* __restrict__ Wi,
                               const float* __restrict__ Wh,
                               const float* __restrict__ bi,
                               const float* __restrict__ bh) {
    int stride = gridDim.x * blockDim.x;
    int tid0 = blockIdx.x * blockDim.x + threadIdx.x;
    for (int idx = tid0; idx < G_ * H_; idx += stride) {
        int jp = idx / H_, i = idx % H_;
        int gate = jp & 3, hh = jp >> 2;
        g_Whp_h[idx] = __float2half_rn(Wh[(size_t)(gate * H_ + hh) * H_ + i]);
    }
    for (int idx = tid0; idx < G_ * I_; idx += stride) {
        int jp = idx / I_, i = idx % I_;
        int gate = jp & 3, hh = jp >> 2;
        g_Wip_h[idx] = __float2half_rn(Wi[(size_t)(gate * H_ + hh) * I_ + i]);
    }
    for (int idx = tid0; idx < G_; idx += stride) {
        int gate = idx & 3, hh = idx >> 2;
        int j = gate * H_ + hh;
        g_biasp[idx] = bi[j] + bh[j];
    }
    for (int idx = tid0; idx < B_ * H_; idx += stride) {
        g_h_h[0][idx] = __float2half_rn(0.0f);
    }
    for (int idx = tid0; idx < T_; idx += stride) g_bar[idx] = 0u;
}

__global__ void cvt_x_k(const float* __restrict__ x) {
    size_t n4 = (size_t)B_ * T_ * I_ / 4;
    size_t stride = (size_t)gridDim.x * blockDim.x;
    for (size_t i = blockIdx.x * blockDim.x + threadIdx.x; i < n4; i += stride) {
        float4 v = ((const float4*)x)[i];
        __half2* d = (__half2*)(g_x_h + i * 4);
        d[0] = __floats2half2_rn(v.x, v.y);
        d[1] = __floats2half2_rn(v.z, v.w);
    }
}

// ==================== pregemm (unchanged) ====================
__device__ __forceinline__ void p_load_stage(uint32_t sb,
                                             const __half* a_h, const __half* b_h, int tid) {
    {
        int r = tid >> 2, u = tid & 3;
        uint32_t so = (uint32_t)(r * ASTRIDE_B + u * 16);
        CP16(sb + P_AH + so, a_h + (size_t)r * I_ + u * 8);
    }
    if (tid >= 256) {
        int t2 = tid - 256;
        int r = t2 >> 2, u = t2 & 3;
        uint32_t so = (uint32_t)(r * ASTRIDE_B + u * 16);
        CP16(sb + P_BH + so, b_h + (size_t)r * I_ + u * 8);
    }
}

__global__ void __launch_bounds__(512, 2) pregemm_k() {
    extern __shared__ char smem[];
    const uint32_t sm0 = smem_u32(smem);
    const int tid = threadIdx.x;
    const int wid = tid >> 5, lane = tid & 31;
    const int mb = blockIdx.x * 128;
    const int cb = blockIdx.y * 64;

    const __half* a_h = g_x_h + (size_t)mb * I_;
    const __half* b_h = g_Wip_h + (size_t)cb * I_;

    float acc[4][4] = {};

#pragma unroll
    for (int s = 0; s < 2; s++) {
        p_load_stage(sm0 + s * P_STAGE, a_h + s * 32, b_h + s * 32, tid);
        CP_COMMIT();
    }
#pragma unroll 1
    for (int ch = 0; ch < 16; ch++) {
        CP_WAIT1();
        __syncthreads();
        if (ch + 2 < 16) {
            int s = (ch + 2) % 3;
            p_load_stage(sm0 + s * P_STAGE, a_h + (ch + 2) * 32, b_h + (ch + 2) * 32, tid);
        }
        CP_COMMIT();
        compute_chunk(sm0 + (ch % 3) * P_STAGE, P_BH, wid, lane, acc);
    }

    const int wm = (wid >> 1) * 16;
    const int wn = (wid & 1) * 32;
    const int qr = lane >> 2, qc = 2 * (lane & 3);
#pragma unroll
    for (int half = 0; half < 2; half++) {
        int r = wm + qr + half * 8;
        int m = mb + r;
        int b = m >> 9, tt = m & 511;
        float* preh = (tt < 256 ? g_pre0 : g_pre1);
        float* dst = preh + (size_t)(tt & 255) * B_ * G_ + (size_t)b * G_ + cb;
#pragma unroll
        for (int nt = 0; nt < 4; nt++) {
            int col = wn + nt * 8 + qc;
            dst[col]     = acc[nt][half * 2 + 0] + g_biasp[cb + col];
            dst[col + 1] = acc[nt][half * 2 + 1] + g_biasp[cb + col + 1];
        }
    }
}

// ==================== PERSISTENT LSTM recurrence (W-stationary, reg epilogue) ====================
__device__ __forceinline__ float sigm(float v) { return 1.0f / (1.0f + expf(-v)); }

__global__ void __launch_bounds__(S_NTOT, 1) lstm_persist_k(float* __restrict__ c,
                                                            const float* __restrict__ c0) {
    extern __shared__ char smem[];
    const uint32_t sm0 = smem_u32(smem);
    const int tid = threadIdx.x;
    const int wid = tid >> 5, lane = tid & 31;
    const int rb = (blockIdx.x & 1) * 128;      // batch tile (M=128)
    const int cb = (blockIdx.x >> 1) * 64;      // j' tile
    const int hb = cb >> 2;

    const uint32_t mb_full = sm0 + S_MBAR;
    const uint32_t mb_cons = sm0 + S_MBAR + 32;
    const uint32_t pre_mb  = sm0 + S_MBAR + 64;

    if (tid == 0) {
#pragma unroll
        for (int s = 0; s < S_NSTAGE; s++) {
            MBARRIER_INIT(mb_full + s * 8, S_NPROD);   // 128 noinc async arrivals
            MBARRIER_INIT(mb_cons + s * 8, 16);        // 16 consumer-warp arrivals
        }
        MBARRIER_INIT(pre_mb, 16);                     // consumers done reading pre
    }

    // ---- load W resident tile once: 32 chunks x 64 rows x 64B, XOR swizzle ----
    {
        const __half* wsrc = g_Whp_h + (size_t)cb * H_;
        for (int i = tid; i < 8192; i += S_NTOT) {
            int ch = i >> 8, r = (i >> 2) & 63, u = i & 3;
            uint32_t off = (uint32_t)(ch * 4096 + r * 64 + ((u ^ ((r >> 1) & 3)) << 4));
            CP16(sm0 + S_W + off, wsrc + (size_t)r * H_ + ch * 32 + u * 8);
        }
    }
    CP_WAIT_ALL();
    __syncthreads();

    // ---- epilogue geometry + c in REGISTERS for the whole recurrence ----
    const int wm = (wid >> 1) * 16;
    const int wn = (wid & 1) * 32;
    const int qr = lane >> 2;
    const int ep_row = wm + qr + ((lane & 1) ? 8 : 0);   // row this lane owns
    const int hh_base = (wn + ((lane & 2) << 1)) >> 2;   // + 2*nt per nt
    float creg[4];
    if (wid < 16) {
#pragma unroll
        for (int nt = 0; nt < 4; nt++)
            creg[nt] = c0[(size_t)(rb + ep_row) * H_ + hb + hh_base + 2 * nt];
    }

#pragma unroll 1
    for (int t = 0; t < T_; t++) {
        const float* prebase = (t < 256 ? g_pre0 : g_pre1) + (size_t)(t & 255) * B_ * G_;
        const __half* a_h = g_h_h[t & 1] + (size_t)rb * H_;
        __half* __restrict__ hout = g_h_h[(t & 1) ^ 1];

        if (wid >= 16) {
            // ======== PRODUCER warps (4 warps): stream A chunks ========
            const int ptid = tid - S_NCONS;    // 0..127
#pragma unroll 1
            for (int ch = 0; ch < 32; ch++) {
                const int q = (t << 5) + ch;   // continuous chunk counter
                const int s = q & 3;
                if (q >= 4) MBARRIER_WAIT_PARITY(mb_cons + s * 8, ((q >> 2) - 1) & 1);
                const uint32_t sb = sm0 + S_STAGEA + s * S_ASTG;
                const int k0 = ch * 32;
#pragma unroll
                for (int j = 0; j < 4; j++) {
                    int u = ptid + j * S_NPROD;
                    int r = u >> 2, c16 = u & 3;
                    CP16(sb + (uint32_t)(r * ASTRIDE_B + c16 * 16),
                         a_h + (size_t)r * H_ + k0 + c16 * 8);
                }
                CP_MBAR_ARRIVE_NOINC(mb_full + s * 8);
                if (t == 0 && ch == 0) {
                    // pre[0]: 2048 units, covered by chunk-1 arrive
#pragma unroll
                    for (int j = 0; j < 16; j++) {
                        int u = ptid + j * S_NPROD;
                        int r = u >> 4, qd = u & 15;
                        CP16(sm0 + S_PRE + (uint32_t)u * 16,
                             prebase + (size_t)(rb + r) * G_ + cb + qd * 4);
                    }
                }
            }
            // prefetch pre[t+1] once consumers have read pre[t] (overlaps epilogue+barrier)
            if (t + 1 < T_) {
                MBARRIER_WAIT_PARITY(pre_mb, t & 1);
                const float* prenext = (t + 1 < 256 ? g_pre0 : g_pre1)
                                       + (size_t)((t + 1) & 255) * B_ * G_;
#pragma unroll
                for (int j = 0; j < 16; j++) {
                    int u = (tid - S_NCONS) + j * S_NPROD;
                    int r = u >> 4, qd = u & 15;
                    CP16(sm0 + S_PRE + (uint32_t)u * 16,
                         prenext + (size_t)(rb + r) * G_ + cb + qd * 4);
                }
            }
        } else {
            // ======== CONSUMER warps (16): mainloop then register epilogue ========
            float acc[4][4] = {};
#pragma unroll 1
            for (int ch = 0; ch < 32; ch++) {
                const int q = (t << 5) + ch;
                const int s = q & 3;
                MBARRIER_WAIT_PARITY(mb_full + s * 8, (q >> 2) & 1);
                compute_chunk_w(sm0 + S_STAGEA + s * S_ASTG,
                                sm0 + S_W + (uint32_t)(ch * 4096), wid, lane, acc);
                __syncwarp();
                if (lane == 0) MBARRIER_ARRIVE(mb_cons + s * 8);
            }

            // ---- register epilogue: exchange gate halves within lane pairs ----
            const float4* PreS = (const float4*)(smem + S_PRE);
#pragma unroll
            for (int nt = 0; nt < 4; nt++) {
                float p0 = __shfl_xor_sync(0xFFFFFFFFu, acc[nt][0], 1);
                float p1 = __shfl_xor_sync(0xFFFFFFFFu, acc[nt][1], 1);
                float p2 = __shfl_xor_sync(0xFFFFFFFFu, acc[nt][2], 1);
                float p3 = __shfl_xor_sync(0xFFFFFFFFu, acc[nt][3], 1);
                float gi, gf, gg, go;
                if ((lane & 1) == 0) { gi = acc[nt][0]; gf = acc[nt][1]; gg = p0; go = p1; }
                else                 { gi = p2; gf = p3; gg = acc[nt][2]; go = acc[nt][3]; }
                int hh = hh_base + 2 * nt;
                float4 p = PreS[ep_row * 16 + hh];
                float iv = sigm(gi + p.x);
                float fv = sigm(gf + p.y);
                float gv = tanhf(gg + p.z);
                float ov = sigm(go + p.w);
                float cn = fv * creg[nt] + iv * gv;
                creg[nt] = cn;
                hout[(size_t)(rb + ep_row) * H_ + hb + hh] = __float2half_rn(ov * tanhf(cn));
            }
            __syncwarp();
            if (lane == 0) MBARRIER_ARRIVE(pre_mb);   // pre[t] consumed
        }

        // ---- grid-wide barrier (h must be visible before next step's A loads) ----
        __threadfence();
        __syncthreads();
        if (tid == 0) {
            atomicAdd(&g_bar[t], 1u);
            while (*(volatile unsigned*)&g_bar[t] < NBLK) {}
            __threadfence();
        }
        __syncthreads();
    }

    // ---- final: write register-resident c to output ----
    if (wid < 16) {
#pragma unroll
        for (int nt = 0; nt < 4; nt++)
            c[(size_t)(rb + ep_row) * H_ + hb + hh_base + 2 * nt] = creg[nt];
    }
}

// ==================== launch ====================
extern "C" void kernel_launch(void* const* d_in, const int* in_sizes, int n_in,
                              void* d_out, int out_size) {
    const float* x  = (const float*)d_in[0];
    const float* Wi = (const float*)d_in[1];
    const float* Wh = (const float*)d_in[2];
    const float* bi = (const float*)d_in[3];
    const float* bh = (const float*)d_in[4];
    const float* c0 = (const float*)d_in[5];
    float* c = (float*)d_out;

    static bool attr_set = false;
    if (!attr_set) {
        cudaFuncSetAttribute(pregemm_k, cudaFuncAttributeMaxDynamicSharedMemorySize, P_SMEM);
        cudaFuncSetAttribute(lstm_persist_k, cudaFuncAttributeMaxDynamicSharedMemorySize, S_SMEM);
        attr_set = true;
    }

    cvt_x_k<<<4096, 256>>>(x);
    permute_init_k<<<512, 256>>>(Wi, Wh, bi, bh);   // also resets g_bar

    pregemm_k<<<dim3((B_ * T_) / 128, G_ / 64), 512, P_SMEM>>>();

    lstm_persist_k<<<NBLK, S_NTOT, S_SMEM>>>(c, c0);
}